// round 10
// baseline (speedup 1.0000x reference)
#include <cuda_runtime.h>
#include <cuda_fp16.h>
#include <math.h>
#include <cstdint>

#define Dm   2048
#define Bb   2
#define Sseq 2048
#define Hh   16
#define DKk  128
#define Mrows 4096
#define KP2  4096          // 2 * 2048 (fp16 two-term split packed along K)
#define KT64 (KP2 / 64)    // 64 K-slabs of 64
#define SCALE 0.08838834764831844055f  // 1/sqrt(128)

__device__ float g_invf[64];

// fp16 two-term split GEMM operands
__device__ __half g_Ax[(size_t)Mrows * KP2];    // [hi|lo]
__device__ __half g_Aao[(size_t)Mrows * KP2];   // [hi|lo]
__device__ __half g_Wq[(size_t)Dm * KP2];       // [hi|hi]
__device__ __half g_Wk[(size_t)Dm * KP2];
__device__ __half g_Wv[(size_t)Dm * KP2];
__device__ __half g_Wo[(size_t)Dm * KP2];

// per-head fp16 Q/K/V for flash:  [bh][s][128]
#define HS ((size_t)32 * 2048 * 128)
__device__ __half g_Qh[HS];
__device__ __half g_Ql[HS];
__device__ __half g_Kh[HS];
__device__ __half g_Vh[HS];

__device__ __forceinline__ uint32_t smem_to_u32(const void* p) {
    uint32_t a;
    asm("{ .reg .u64 t; cvta.to.shared.u64 t, %1; cvt.u32.u64 %0, t; }"
        : "=r"(a) : "l"(p));
    return a;
}
__device__ __forceinline__ void cpa16(uint32_t d, const void* g) {
    asm volatile("cp.async.cg.shared.global [%0], [%1], 16;" :: "r"(d), "l"(g) : "memory");
}
__device__ __forceinline__ uint32_t pack_f16x2(float lo, float hi) {
    uint32_t r;
    asm("cvt.rn.f16x2.f32 %0, %1, %2;" : "=r"(r) : "f"(hi), "f"(lo));
    return r;
}
__device__ __forceinline__ float f16rt(float x) {
    return __half2float(__float2half_rn(x));
}
__device__ __forceinline__ void split_pair(float v0, float v1, uint32_t& hi, uint32_t& lo) {
    hi = pack_f16x2(v0, v1);
    lo = pack_f16x2(v0 - f16rt(v0), v1 - f16rt(v1));
}

#define LDSM4(R, addr) \
    asm volatile("ldmatrix.sync.aligned.m8n8.x4.shared.b16 {%0,%1,%2,%3}, [%4];" \
        : "=r"((R)[0]), "=r"((R)[1]), "=r"((R)[2]), "=r"((R)[3]) : "r"(addr))
#define LDSM4T(R, addr) \
    asm volatile("ldmatrix.sync.aligned.m8n8.x4.trans.shared.b16 {%0,%1,%2,%3}, [%4];" \
        : "=r"((R)[0]), "=r"((R)[1]), "=r"((R)[2]), "=r"((R)[3]) : "r"(addr))
#define MMA16816(C, A, B0, B1) \
    asm volatile("mma.sync.aligned.m16n8k16.row.col.f32.f16.f16.f32 " \
        "{%0,%1,%2,%3}, {%4,%5,%6,%7}, {%8,%9}, {%0,%1,%2,%3};" \
        : "+f"((C)[0]), "+f"((C)[1]), "+f"((C)[2]), "+f"((C)[3]) \
        : "r"((A)[0]), "r"((A)[1]), "r"((A)[2]), "r"((A)[3]), "r"(B0), "r"(B1))

// ===========================================================================
// fp32 [R,2048] -> fp16 two-term packed [R,4096].
//   dup=0 (A operands): [hi|lo]   dup=1 (W operands): [hi|hi]
// ===========================================================================
__device__ __forceinline__
void conv_body(const float* __restrict__ X, __half* __restrict__ Y,
               int dup, int idx)
{
    int r  = idx >> 9;
    int c4 = idx & 511;
    float4 v = *(const float4*)(X + ((size_t)r << 11) + (c4 << 2));
    __half h0 = __float2half_rn(v.x), h1 = __float2half_rn(v.y);
    __half h2 = __float2half_rn(v.z), h3 = __float2half_rn(v.w);
    __half l0 = __float2half_rn(v.x - __half2float(h0));
    __half l1 = __float2half_rn(v.y - __half2float(h1));
    __half l2 = __float2half_rn(v.z - __half2float(h2));
    __half l3 = __float2half_rn(v.w - __half2float(h3));
    size_t row = (size_t)r * KP2;
    __half2 hA = __halves2half2(h0, h1), hB = __halves2half2(h2, h3);
    __half2 lA = __halves2half2(l0, l1), lB = __halves2half2(l2, l3);
    __half2* p0 = (__half2*)(Y + row + (c4 << 2));
    __half2* p1 = (__half2*)(Y + row + 2048 + (c4 << 2));
    p0[0] = hA; p0[1] = hB;
    if (dup) { p1[0] = hA; p1[1] = hB; }
    else     { p1[0] = lA; p1[1] = lB; }
}

// One launch: RoPE freqs + x split + 4 weight splits.
// blocks [0,8192): x.   [8192, 8192+4*4096): weights.
__global__ __launch_bounds__(256)
void prep(const float* __restrict__ x,
          const float* __restrict__ W0, const float* __restrict__ W1,
          const float* __restrict__ W2, const float* __restrict__ W3,
          __half* __restrict__ Yx,
          __half* __restrict__ Y0, __half* __restrict__ Y1,
          __half* __restrict__ Y2, __half* __restrict__ Y3)
{
    int bid = blockIdx.x, tid = threadIdx.x;
    if (bid == 0 && tid < 64)
        g_invf[tid] = (float)pow(10000.0, -(double)tid / 64.0);

    if (bid < 8192) {
        conv_body(x, Yx, 0, bid * 256 + tid);
    } else {
        int w   = (bid - 8192) >> 12;            // 0..3
        int sub = (bid - 8192) & 4095;
        const float* W = (w == 0) ? W0 : (w == 1) ? W1 : (w == 2) ? W2 : W3;
        __half*      Y = (w == 0) ? Y0 : (w == 1) ? Y1 : (w == 2) ? Y2 : Y3;
        conv_body(W, Y, 1, sub * 256 + tid);
    }
}

// ===========================================================================
// GEMM mainloop: CTA 128x128, BK=64 (pitch 144B), 3-stage cp.async,
// 8 warps (2x4), warp 64x32 — validated round-8/9 shape, K'=4096.
// ===========================================================================
#define SPITCH 144u
#define STG_OP (128u * SPITCH)          // 18432 B per operand per stage
#define STG_BOTH (2u * STG_OP)          // 36864 per stage
#define GSMEM (3u * STG_BOTH)           // 110592 total

__device__ __forceinline__
void gemm_mainloop(const __half* __restrict__ A,
                   const __half* __restrict__ B,
                   float c[4][4][4])
{
    extern __shared__ __align__(128) char gsm[];
    const uint32_t sbase = smem_to_u32(gsm);
    const int tid = threadIdx.x;
    const int lane = tid & 31, wid = tid >> 5;
    const int bm = blockIdx.y * 128, bn = blockIdx.x * 128;
    const int wm = (wid >> 2) * 64, wn = (wid & 3) * 32;

    const __half* Ag = A + (size_t)bm * KP2;
    const __half* Bg = B + (size_t)bn * KP2;

#pragma unroll
    for (int i = 0; i < 4; i++)
#pragma unroll
        for (int j = 0; j < 4; j++)
#pragma unroll
            for (int k = 0; k < 4; k++) c[i][j][k] = 0.f;

    const int frow = tid >> 3;          // 0..31 (+32*j)
    const int fseg = tid & 7;           // 0..7

#define GFILL(s) do {                                                         \
        uint32_t _st = sbase + (uint32_t)((s) % 3) * STG_BOTH;                \
        int _ks = (s) * 64;                                                   \
        _Pragma("unroll")                                                     \
        for (int _j = 0; _j < 4; _j++) {                                      \
            int _row = frow + _j * 32;                                        \
            uint32_t _d = (uint32_t)(_row * SPITCH + fseg * 16);              \
            const void* _ga = Ag + (size_t)_row * KP2 + _ks + fseg * 8;       \
            const void* _gb = Bg + (size_t)_row * KP2 + _ks + fseg * 8;       \
            cpa16(_st + _d, _ga); cpa16(_st + STG_OP + _d, _gb);              \
        }                                                                     \
        asm volatile("cp.async.commit_group;" ::: "memory");                  \
    } while (0)

    GFILL(0); GFILL(1);

    const uint32_t aRowOff = (uint32_t)((wm + (lane & 15)) * SPITCH);
    const uint32_t bRowOff = (uint32_t)((wn + (lane & 7) + ((lane >> 4) << 3)) * SPITCH);
    const uint32_t aColOff = (uint32_t)((lane >> 4) << 4);
    const uint32_t bColOff = (uint32_t)(((lane >> 3) & 1) << 4);

    for (int kt = 0; kt < KT64; kt++) {
        asm volatile("cp.async.wait_group 1;" ::: "memory");
        __syncthreads();
        if (kt + 2 < KT64) { GFILL(kt + 2); }
        else { asm volatile("cp.async.commit_group;" ::: "memory"); }

        const uint32_t st = sbase + (uint32_t)(kt % 3) * STG_BOTH;
        const uint32_t sa = st, sb = st + STG_OP;

#pragma unroll
        for (int ks = 0; ks < 4; ks++) {
            uint32_t a[4][4], bf[2][4];
            const uint32_t ac = ks * 32 + aColOff;
            const uint32_t bc = ks * 32 + bColOff;
#pragma unroll
            for (int mt = 0; mt < 4; mt++)
                LDSM4(a[mt], sa + aRowOff + (uint32_t)(mt * 16) * SPITCH + ac);
#pragma unroll
            for (int nt2 = 0; nt2 < 2; nt2++)
                LDSM4(bf[nt2], sb + bRowOff + (uint32_t)(nt2 * 16) * SPITCH + bc);
#pragma unroll
            for (int mt = 0; mt < 4; mt++)
#pragma unroll
                for (int nt = 0; nt < 4; nt++)
                    MMA16816(c[mt][nt], a[mt],
                             bf[nt >> 1][(nt & 1) * 2], bf[nt >> 1][(nt & 1) * 2 + 1]);
        }
    }
#undef GFILL
}

// ===========================================================================
// QKV GEMM with fused RoPE + scale + fp16-split epilogue.
// z=0: Q -> hi+lo;  z=1: K -> hi only;  z=2: V -> hi only.
// ===========================================================================
__global__ __launch_bounds__(256, 2)
void gemm_qkv_fused(const __half* __restrict__ A,
                    const __half* __restrict__ WQ, const __half* __restrict__ WK,
                    const __half* __restrict__ WV,
                    const int* __restrict__ pos)
{
    const int z = blockIdx.z;
    const __half* Bw = (z == 0) ? WQ : (z == 1) ? WK : WV;

    float c[4][4][4];
    gemm_mainloop(A, Bw, c);

    __half* HI = (z == 0) ? g_Qh : (z == 1) ? g_Kh : g_Vh;

    const int lane = threadIdx.x & 31, wid = threadIdx.x >> 5;
    const int bm = blockIdx.y * 128, bn = blockIdx.x * 128;
    const int wm = (wid >> 2) * 64, wn = (wid & 3) * 32;
    const int r0 = bm + wm + (lane >> 2);
    const int c0 = bn + wn + (lane & 3) * 2;

#pragma unroll
    for (int mt = 0; mt < 4; mt++) {
#pragma unroll
        for (int half = 0; half < 2; half++) {
            const int rr = r0 + mt * 16 + half * 8;
            const int b = rr >> 11, s = rr & 2047;
            const int p = pos[s];
#pragma unroll
            for (int nt = 0; nt < 4; nt++) {
                const int cc = c0 + nt * 8;
                const int h = cc >> 7, dk = cc & 127;
                float v0 = c[mt][nt][half * 2], v1 = c[mt][nt][half * 2 + 1];
                if (z < 2) {
                    const int i = dk >> 1;
                    float ang = (float)p * g_invf[i];
                    float sn, cs;
                    sincosf(ang, &sn, &cs);
                    float r1 = v0 * cs - v1 * sn;
                    float r2 = v0 * sn + v1 * cs;
                    v0 = r1; v1 = r2;
                    if (z == 0) { v0 *= SCALE; v1 *= SCALE; }
                }
                size_t dst = (((size_t)(b * 16 + h) << 11) + s) * 128 + dk;
                if (z == 0) {
                    uint32_t hi, lo;
                    split_pair(v0, v1, hi, lo);
                    *(uint32_t*)(HI + dst)   = hi;
                    *(uint32_t*)(g_Ql + dst) = lo;
                } else {
                    *(uint32_t*)(HI + dst) = pack_f16x2(v0, v1);
                }
            }
        }
    }
}

// ===========================================================================
// Final GEMM: out = AO' * WO'^T, plain fp32 epilogue
// ===========================================================================
__global__ __launch_bounds__(256, 2)
void gemm_out(const __half* __restrict__ A, const __half* __restrict__ B,
              float* __restrict__ C)
{
    float c[4][4][4];
    gemm_mainloop(A, B, c);

    const int lane = threadIdx.x & 31, wid = threadIdx.x >> 5;
    const int bm = blockIdx.y * 128, bn = blockIdx.x * 128;
    const int wm = (wid >> 2) * 64, wn = (wid & 3) * 32;
    const int r0 = bm + wm + (lane >> 2);
    const int c0 = bn + wn + (lane & 3) * 2;
#pragma unroll
    for (int mt = 0; mt < 4; mt++)
#pragma unroll
        for (int nt = 0; nt < 4; nt++) {
            int rr = r0 + mt * 16, cc = c0 + nt * 8;
            *(float2*)(C + (size_t)rr * Dm + cc)       = make_float2(c[mt][nt][0], c[mt][nt][1]);
            *(float2*)(C + (size_t)(rr + 8) * Dm + cc) = make_float2(c[mt][nt][2], c[mt][nt][3]);
        }
}

// ===========================================================================
// Tensor-core flash attention, fp16 two-term, causal.
// BQ=128 (256 threads, 8 warps, warp owns 16 q-rows), BKV=64.
// smem: Qh[128], Ql[128], Kh[64], Vh[64] tiles -> 104448 B, 2 CTA/SM.
// ===========================================================================
#define FPB 272
#define QTILEB ((uint32_t)(128 * FPB))   // 34816
#define KTILEB ((uint32_t)(64 * FPB))    // 17408
#define FSMEM  (2u * QTILEB + 2u * KTILEB)  // 104448

__global__ __launch_bounds__(256, 2)
void flash_f16(const __half* __restrict__ Qh, const __half* __restrict__ Ql,
               const __half* __restrict__ Kh, const __half* __restrict__ Vh,
               __half* __restrict__ AO)
{
    extern __shared__ __align__(128) __half fsm[];
    const uint32_t sb = smem_to_u32(fsm);
    const uint32_t uQh = sb,                 uQl = sb + QTILEB;
    const uint32_t uKh = sb + 2 * QTILEB,    uVh = sb + 2 * QTILEB + KTILEB;

    const int tid = threadIdx.x, lane = tid & 31, wid = tid >> 5;
    const int qt = (int)gridDim.x - 1 - (int)blockIdx.x;    // largest first
    const int bh = blockIdx.y;
    const int q0 = qt * 128;
    const size_t hbase = (size_t)bh * (2048 * 128);

    // Q tiles (128 rows) -> smem
#pragma unroll
    for (int i = 0; i < 8; i++) {
        int cc = tid + i * 256, row = cc >> 4, seg = cc & 15;
        uint32_t d = (uint32_t)(row * FPB + seg * 16);
        size_t g = hbase + (size_t)(q0 + row) * 128 + seg * 8;
        cpa16(uQh + d, Qh + g);
        cpa16(uQl + d, Ql + g);
    }
    asm volatile("cp.async.commit_group;" ::: "memory");

#define KVFILL(jj) do {                                                        \
        int _c0 = (jj) * 64;                                                   \
        _Pragma("unroll")                                                      \
        for (int _i = 0; _i < 4; _i++) {                                       \
            int _cc = tid + _i * 256, _row = _cc >> 4, _seg = _cc & 15;        \
            uint32_t _d = (uint32_t)(_row * FPB + _seg * 16);                  \
            size_t _g = hbase + (size_t)(_c0 + _row) * 128 + _seg * 8;         \
            cpa16(uKh + _d, Kh + _g);                                          \
            cpa16(uVh + _d, Vh + _g);                                          \
        }                                                                      \
        asm volatile("cp.async.commit_group;" ::: "memory");                   \
    } while (0)

    KVFILL(0);

    float co[16][4];
#pragma unroll
    for (int i = 0; i < 16; i++)
#pragma unroll
        for (int k = 0; k < 4; k++) co[i][k] = 0.f;
    float m0v = -1e30f, m1v = -1e30f, l0v = 0.f, l1v = 0.f;

    const uint32_t aoff  = (uint32_t)((wid * 16 + (lane & 15)) * FPB + ((lane >> 4) << 4));
    const uint32_t bKoff = (uint32_t)(((lane & 7) + ((lane >> 4) << 3)) * FPB + (((lane >> 3) & 1) << 4));
    const uint32_t vloff = (uint32_t)((lane & 15) * FPB + ((lane >> 4) << 4));

    const int ntiles = 2 * qt + 2;
    for (int j = 0; j < ntiles; j++) {
        asm volatile("cp.async.wait_group 0;" ::: "memory");
        __syncthreads();

        float cs[8][4];
#pragma unroll
        for (int i = 0; i < 8; i++)
#pragma unroll
            for (int k = 0; k < 4; k++) cs[i][k] = 0.f;

#pragma unroll
        for (int ks = 0; ks < 8; ks++) {
            uint32_t aH[4], aL[4];
            LDSM4(aH, uQh + aoff + ks * 32);
            LDSM4(aL, uQl + aoff + ks * 32);
#pragma unroll
            for (int np = 0; np < 4; np++) {
                uint32_t bH[4];
                uint32_t bo = bKoff + (uint32_t)(np * 16 * FPB) + ks * 32;
                LDSM4(bH, uKh + bo);
                MMA16816(cs[2*np],   aH, bH[0], bH[1]);
                MMA16816(cs[2*np+1], aH, bH[2], bH[3]);
                MMA16816(cs[2*np],   aL, bH[0], bH[1]);
                MMA16816(cs[2*np+1], aL, bH[2], bH[3]);
            }
        }

        // causal mask on the two diagonal-region tiles (global coords)
        if (j >= 2 * qt) {
            const int coff = (j - 2 * qt) * 64;    // 0 or 64
            int g = lane >> 2, t2 = (lane & 3) * 2;
            int r0 = wid * 16 + g, r1 = r0 + 8;
#pragma unroll
            for (int nt = 0; nt < 8; nt++) {
                int cl = coff + nt * 8 + t2;
                if (cl     > r0) cs[nt][0] = -1e30f;
                if (cl + 1 > r0) cs[nt][1] = -1e30f;
                if (cl     > r1) cs[nt][2] = -1e30f;
                if (cl + 1 > r1) cs[nt][3] = -1e30f;
            }
        }

        float mx0 = -1e30f, mx1 = -1e30f;
#pragma unroll
        for (int nt = 0; nt < 8; nt++) {
            mx0 = fmaxf(mx0, fmaxf(cs[nt][0], cs[nt][1]));
            mx1 = fmaxf(mx1, fmaxf(cs[nt][2], cs[nt][3]));
        }
        mx0 = fmaxf(mx0, __shfl_xor_sync(0xffffffffu, mx0, 1));
        mx0 = fmaxf(mx0, __shfl_xor_sync(0xffffffffu, mx0, 2));
        mx1 = fmaxf(mx1, __shfl_xor_sync(0xffffffffu, mx1, 1));
        mx1 = fmaxf(mx1, __shfl_xor_sync(0xffffffffu, mx1, 2));
        float mn0 = fmaxf(m0v, mx0), mn1 = fmaxf(m1v, mx1);
        float al0 = __expf(m0v - mn0), al1 = __expf(m1v - mn1);
        m0v = mn0; m1v = mn1;
        float rs0 = 0.f, rs1 = 0.f;
#pragma unroll
        for (int nt = 0; nt < 8; nt++) {
            cs[nt][0] = __expf(cs[nt][0] - mn0);
            cs[nt][1] = __expf(cs[nt][1] - mn0);
            cs[nt][2] = __expf(cs[nt][2] - mn1);
            cs[nt][3] = __expf(cs[nt][3] - mn1);
            rs0 += cs[nt][0] + cs[nt][1];
            rs1 += cs[nt][2] + cs[nt][3];
        }
        rs0 += __shfl_xor_sync(0xffffffffu, rs0, 1);
        rs0 += __shfl_xor_sync(0xffffffffu, rs0, 2);
        rs1 += __shfl_xor_sync(0xffffffffu, rs1, 1);
        rs1 += __shfl_xor_sync(0xffffffffu, rs1, 2);
        l0v = l0v * al0 + rs0;
        l1v = l1v * al1 + rs1;
#pragma unroll
        for (int nt = 0; nt < 16; nt++) {
            co[nt][0] *= al0; co[nt][1] *= al0;
            co[nt][2] *= al1; co[nt][3] *= al1;
        }

#pragma unroll
        for (int ks = 0; ks < 4; ks++) {
            float p0 = cs[2*ks][0],   p1 = cs[2*ks][1],   p2 = cs[2*ks][2],   p3 = cs[2*ks][3];
            float p4 = cs[2*ks+1][0], p5 = cs[2*ks+1][1], p6 = cs[2*ks+1][2], p7 = cs[2*ks+1][3];
            uint32_t aPh[4] = { pack_f16x2(p0, p1), pack_f16x2(p2, p3),
                                pack_f16x2(p4, p5), pack_f16x2(p6, p7) };
            uint32_t aPl[4] = {
                pack_f16x2(p0 - f16rt(p0), p1 - f16rt(p1)),
                pack_f16x2(p2 - f16rt(p2), p3 - f16rt(p3)),
                pack_f16x2(p4 - f16rt(p4), p5 - f16rt(p5)),
                pack_f16x2(p6 - f16rt(p6), p7 - f16rt(p7)) };
            uint32_t vb = vloff + (uint32_t)(ks * 16 * FPB);
#pragma unroll
            for (int dc = 0; dc < 8; dc++) {
                uint32_t vH[4];
                LDSM4T(vH, uVh + vb + dc * 32);
                MMA16816(co[2*dc],   aPh, vH[0], vH[1]);
                MMA16816(co[2*dc+1], aPh, vH[2], vH[3]);
                MMA16816(co[2*dc],   aPl, vH[0], vH[1]);
                MMA16816(co[2*dc+1], aPl, vH[2], vH[3]);
            }
        }

        __syncthreads();
        if (j + 1 < ntiles) KVFILL(j + 1);
    }
#undef KVFILL

    // ---- epilogue: write AO' packed [hi|lo] fp16 directly ----
    float i0 = 1.f / l0v, i1 = 1.f / l1v;
    const int b = bh >> 4, h = bh & 15;
    int g = lane >> 2, t2 = (lane & 3) * 2;
    const int r0 = b * 2048 + q0 + wid * 16 + g;
    const int cbase = h * 128 + t2;
#pragma unroll
    for (int nt = 0; nt < 16; nt++) {
        const int cc = cbase + nt * 8;
        uint32_t hi0, lo0, hi1, lo1;
        split_pair(co[nt][0] * i0, co[nt][1] * i0, hi0, lo0);
        split_pair(co[nt][2] * i1, co[nt][3] * i1, hi1, lo1);
        __half* row0 = AO + (size_t)r0 * KP2 + cc;
        __half* row1 = AO + (size_t)(r0 + 8) * KP2 + cc;
        *(uint32_t*)(row0)        = hi0;
        *(uint32_t*)(row0 + 2048) = lo0;
        *(uint32_t*)(row1)        = hi1;
        *(uint32_t*)(row1 + 2048) = lo1;
    }
}

// ===========================================================================
extern "C" void kernel_launch(void* const* d_in, const int* in_sizes, int n_in,
                              void* d_out, int out_size)
{
    const float* x  = (const float*)d_in[0];
    const float* WQ = (const float*)d_in[1];
    const float* WK = (const float*)d_in[2];
    const float* WV = (const float*)d_in[3];
    const float* WO = (const float*)d_in[4];
    const int*  pos = (const int*)d_in[5];
    float* out = (float*)d_out;

    __half *Axp, *Aaop, *Wqp, *Wkp, *Wvp, *Wop;
    __half *Qhp, *Qlp, *Khp, *Vhp;
    cudaGetSymbolAddress((void**)&Axp, g_Ax);
    cudaGetSymbolAddress((void**)&Aaop, g_Aao);
    cudaGetSymbolAddress((void**)&Wqp, g_Wq);
    cudaGetSymbolAddress((void**)&Wkp, g_Wk);
    cudaGetSymbolAddress((void**)&Wvp, g_Wv);
    cudaGetSymbolAddress((void**)&Wop, g_Wo);
    cudaGetSymbolAddress((void**)&Qhp, g_Qh);
    cudaGetSymbolAddress((void**)&Qlp, g_Ql);
    cudaGetSymbolAddress((void**)&Khp, g_Kh);
    cudaGetSymbolAddress((void**)&Vhp, g_Vh);

    prep<<<8192 + 4 * 4096, 256>>>(x, WQ, WK, WV, WO, Axp, Wqp, Wkp, Wvp, Wop);

    cudaFuncSetAttribute(gemm_qkv_fused, cudaFuncAttributeMaxDynamicSharedMemorySize, GSMEM);
    cudaFuncSetAttribute(gemm_out,       cudaFuncAttributeMaxDynamicSharedMemorySize, GSMEM);

    gemm_qkv_fused<<<dim3(Dm / 128, Mrows / 128, 3), 256, GSMEM>>>(Axp, Wqp, Wkp, Wvp, pos);

    cudaFuncSetAttribute(flash_f16, cudaFuncAttributeMaxDynamicSharedMemorySize, FSMEM);
    flash_f16<<<dim3(Sseq / 128, Bb * Hh), 256, FSMEM>>>(Qhp, Qlp, Khp, Vhp, Aaop);

    gemm_out<<<dim3(Dm / 128, Mrows / 128), 256, GSMEM>>>(Aaop, Wop, out);
}

// round 11
// speedup vs baseline: 1.0575x; 1.0575x over previous
#include <cuda_runtime.h>
#include <cuda_fp16.h>
#include <math.h>
#include <cstdint>

#define Dm   2048
#define Bb   2
#define Sseq 2048
#define Hh   16
#define DKk  128
#define Mrows 4096
#define KP2  4096          // 2 * 2048 (fp16 two-term split packed along K)
#define KT64 (KP2 / 64)    // 64 K-slabs of 64
#define SCALE 0.08838834764831844055f  // 1/sqrt(128)

__device__ float g_invf[64];

// fp16 two-term split GEMM operands
__device__ __half g_Ax[(size_t)Mrows * KP2];    // [hi|lo]
__device__ __half g_Aao[(size_t)Mrows * KP2];   // [hi|lo]
__device__ __half g_Wq[(size_t)Dm * KP2];       // [hi|hi]
__device__ __half g_Wk[(size_t)Dm * KP2];
__device__ __half g_Wv[(size_t)Dm * KP2];
__device__ __half g_Wo[(size_t)Dm * KP2];

// per-head fp16 Q/K/V for flash:  [bh][s][128]
#define HS ((size_t)32 * 2048 * 128)
__device__ __half g_Qh[HS];
__device__ __half g_Ql[HS];
__device__ __half g_Kh[HS];
__device__ __half g_Vh[HS];

__device__ __forceinline__ uint32_t smem_to_u32(const void* p) {
    uint32_t a;
    asm("{ .reg .u64 t; cvta.to.shared.u64 t, %1; cvt.u32.u64 %0, t; }"
        : "=r"(a) : "l"(p));
    return a;
}
__device__ __forceinline__ void cpa16(uint32_t d, const void* g) {
    asm volatile("cp.async.cg.shared.global [%0], [%1], 16;" :: "r"(d), "l"(g) : "memory");
}
__device__ __forceinline__ uint32_t pack_f16x2(float lo, float hi) {
    uint32_t r;
    asm("cvt.rn.f16x2.f32 %0, %1, %2;" : "=r"(r) : "f"(hi), "f"(lo));
    return r;
}
__device__ __forceinline__ float f16rt(float x) {
    return __half2float(__float2half_rn(x));
}
__device__ __forceinline__ void split_pair(float v0, float v1, uint32_t& hi, uint32_t& lo) {
    hi = pack_f16x2(v0, v1);
    lo = pack_f16x2(v0 - f16rt(v0), v1 - f16rt(v1));
}

#define LDSM4(R, addr) \
    asm volatile("ldmatrix.sync.aligned.m8n8.x4.shared.b16 {%0,%1,%2,%3}, [%4];" \
        : "=r"((R)[0]), "=r"((R)[1]), "=r"((R)[2]), "=r"((R)[3]) : "r"(addr))
#define LDSM4T(R, addr) \
    asm volatile("ldmatrix.sync.aligned.m8n8.x4.trans.shared.b16 {%0,%1,%2,%3}, [%4];" \
        : "=r"((R)[0]), "=r"((R)[1]), "=r"((R)[2]), "=r"((R)[3]) : "r"(addr))
#define MMA16816(C, A, B0, B1) \
    asm volatile("mma.sync.aligned.m16n8k16.row.col.f32.f16.f16.f32 " \
        "{%0,%1,%2,%3}, {%4,%5,%6,%7}, {%8,%9}, {%0,%1,%2,%3};" \
        : "+f"((C)[0]), "+f"((C)[1]), "+f"((C)[2]), "+f"((C)[3]) \
        : "r"((A)[0]), "r"((A)[1]), "r"((A)[2]), "r"((A)[3]), "r"(B0), "r"(B1))

// ===========================================================================
// fp32 [R,2048] -> fp16 two-term packed [R,4096].
//   dup=0 (A operands): [hi|lo]   dup=1 (W operands): [hi|hi]
// ===========================================================================
__device__ __forceinline__
void conv_body(const float* __restrict__ X, __half* __restrict__ Y,
               int dup, int idx)
{
    int r  = idx >> 9;
    int c4 = idx & 511;
    float4 v = *(const float4*)(X + ((size_t)r << 11) + (c4 << 2));
    __half h0 = __float2half_rn(v.x), h1 = __float2half_rn(v.y);
    __half h2 = __float2half_rn(v.z), h3 = __float2half_rn(v.w);
    __half l0 = __float2half_rn(v.x - __half2float(h0));
    __half l1 = __float2half_rn(v.y - __half2float(h1));
    __half l2 = __float2half_rn(v.z - __half2float(h2));
    __half l3 = __float2half_rn(v.w - __half2float(h3));
    size_t row = (size_t)r * KP2;
    __half2 hA = __halves2half2(h0, h1), hB = __halves2half2(h2, h3);
    __half2 lA = __halves2half2(l0, l1), lB = __halves2half2(l2, l3);
    __half2* p0 = (__half2*)(Y + row + (c4 << 2));
    __half2* p1 = (__half2*)(Y + row + 2048 + (c4 << 2));
    p0[0] = hA; p0[1] = hB;
    if (dup) { p1[0] = hA; p1[1] = hB; }
    else     { p1[0] = lA; p1[1] = lB; }
}

// One launch: RoPE freqs + x split + 4 weight splits.
__global__ __launch_bounds__(256)
void prep(const float* __restrict__ x,
          const float* __restrict__ W0, const float* __restrict__ W1,
          const float* __restrict__ W2, const float* __restrict__ W3,
          __half* __restrict__ Yx,
          __half* __restrict__ Y0, __half* __restrict__ Y1,
          __half* __restrict__ Y2, __half* __restrict__ Y3)
{
    int bid = blockIdx.x, tid = threadIdx.x;
    if (bid == 0 && tid < 64)
        g_invf[tid] = (float)pow(10000.0, -(double)tid / 64.0);

    if (bid < 8192) {
        conv_body(x, Yx, 0, bid * 256 + tid);
    } else {
        int w   = (bid - 8192) >> 12;            // 0..3
        int sub = (bid - 8192) & 4095;
        const float* W = (w == 0) ? W0 : (w == 1) ? W1 : (w == 2) ? W2 : W3;
        __half*      Y = (w == 0) ? Y0 : (w == 1) ? Y1 : (w == 2) ? Y2 : Y3;
        conv_body(W, Y, 1, sub * 256 + tid);
    }
}

// ===========================================================================
// GEMM mainloop: CTA 128x128, BK=64 (pitch 144B), 3-stage cp.async,
// 8 warps (2x4), warp 64x32 — validated round-8/9 shape, K'=4096.
// ===========================================================================
#define SPITCH 144u
#define STG_OP (128u * SPITCH)          // 18432 B per operand per stage
#define STG_BOTH (2u * STG_OP)          // 36864 per stage
#define GSMEM (3u * STG_BOTH)           // 110592 total

__device__ __forceinline__
void gemm_mainloop(const __half* __restrict__ A,
                   const __half* __restrict__ B,
                   float c[4][4][4])
{
    extern __shared__ __align__(128) char gsm[];
    const uint32_t sbase = smem_to_u32(gsm);
    const int tid = threadIdx.x;
    const int lane = tid & 31, wid = tid >> 5;
    const int bm = blockIdx.y * 128, bn = blockIdx.x * 128;
    const int wm = (wid >> 2) * 64, wn = (wid & 3) * 32;

    const __half* Ag = A + (size_t)bm * KP2;
    const __half* Bg = B + (size_t)bn * KP2;

#pragma unroll
    for (int i = 0; i < 4; i++)
#pragma unroll
        for (int j = 0; j < 4; j++)
#pragma unroll
            for (int k = 0; k < 4; k++) c[i][j][k] = 0.f;

    const int frow = tid >> 3;          // 0..31 (+32*j)
    const int fseg = tid & 7;           // 0..7

#define GFILL(s) do {                                                         \
        uint32_t _st = sbase + (uint32_t)((s) % 3) * STG_BOTH;                \
        int _ks = (s) * 64;                                                   \
        _Pragma("unroll")                                                     \
        for (int _j = 0; _j < 4; _j++) {                                      \
            int _row = frow + _j * 32;                                        \
            uint32_t _d = (uint32_t)(_row * SPITCH + fseg * 16);              \
            const void* _ga = Ag + (size_t)_row * KP2 + _ks + fseg * 8;       \
            const void* _gb = Bg + (size_t)_row * KP2 + _ks + fseg * 8;       \
            cpa16(_st + _d, _ga); cpa16(_st + STG_OP + _d, _gb);              \
        }                                                                     \
        asm volatile("cp.async.commit_group;" ::: "memory");                  \
    } while (0)

    GFILL(0); GFILL(1);

    const uint32_t aRowOff = (uint32_t)((wm + (lane & 15)) * SPITCH);
    const uint32_t bRowOff = (uint32_t)((wn + (lane & 7) + ((lane >> 4) << 3)) * SPITCH);
    const uint32_t aColOff = (uint32_t)((lane >> 4) << 4);
    const uint32_t bColOff = (uint32_t)(((lane >> 3) & 1) << 4);

    for (int kt = 0; kt < KT64; kt++) {
        asm volatile("cp.async.wait_group 1;" ::: "memory");
        __syncthreads();
        if (kt + 2 < KT64) { GFILL(kt + 2); }
        else { asm volatile("cp.async.commit_group;" ::: "memory"); }

        const uint32_t st = sbase + (uint32_t)(kt % 3) * STG_BOTH;
        const uint32_t sa = st, sb = st + STG_OP;

#pragma unroll
        for (int ks = 0; ks < 4; ks++) {
            uint32_t a[4][4], bf[2][4];
            const uint32_t ac = ks * 32 + aColOff;
            const uint32_t bc = ks * 32 + bColOff;
#pragma unroll
            for (int mt = 0; mt < 4; mt++)
                LDSM4(a[mt], sa + aRowOff + (uint32_t)(mt * 16) * SPITCH + ac);
#pragma unroll
            for (int nt2 = 0; nt2 < 2; nt2++)
                LDSM4(bf[nt2], sb + bRowOff + (uint32_t)(nt2 * 16) * SPITCH + bc);
#pragma unroll
            for (int mt = 0; mt < 4; mt++)
#pragma unroll
                for (int nt = 0; nt < 4; nt++)
                    MMA16816(c[mt][nt], a[mt],
                             bf[nt >> 1][(nt & 1) * 2], bf[nt >> 1][(nt & 1) * 2 + 1]);
        }
    }
#undef GFILL
}

// ===========================================================================
// QKV GEMM with fused RoPE + scale + fp16-split epilogue.
// z=0: Q -> hi+lo;  z=1: K -> hi only;  z=2: V -> hi only.
// ===========================================================================
__global__ __launch_bounds__(256, 2)
void gemm_qkv_fused(const __half* __restrict__ A,
                    const __half* __restrict__ WQ, const __half* __restrict__ WK,
                    const __half* __restrict__ WV,
                    const int* __restrict__ pos)
{
    const int z = blockIdx.z;
    const __half* Bw = (z == 0) ? WQ : (z == 1) ? WK : WV;

    float c[4][4][4];
    gemm_mainloop(A, Bw, c);

    __half* HI = (z == 0) ? g_Qh : (z == 1) ? g_Kh : g_Vh;

    const int lane = threadIdx.x & 31, wid = threadIdx.x >> 5;
    const int bm = blockIdx.y * 128, bn = blockIdx.x * 128;
    const int wm = (wid >> 2) * 64, wn = (wid & 3) * 32;
    const int r0 = bm + wm + (lane >> 2);
    const int c0 = bn + wn + (lane & 3) * 2;

#pragma unroll
    for (int mt = 0; mt < 4; mt++) {
#pragma unroll
        for (int half = 0; half < 2; half++) {
            const int rr = r0 + mt * 16 + half * 8;
            const int b = rr >> 11, s = rr & 2047;
            const int p = pos[s];
#pragma unroll
            for (int nt = 0; nt < 4; nt++) {
                const int cc = c0 + nt * 8;
                const int h = cc >> 7, dk = cc & 127;
                float v0 = c[mt][nt][half * 2], v1 = c[mt][nt][half * 2 + 1];
                if (z < 2) {
                    const int i = dk >> 1;
                    float ang = (float)p * g_invf[i];
                    float sn, cs;
                    sincosf(ang, &sn, &cs);
                    float r1 = v0 * cs - v1 * sn;
                    float r2 = v0 * sn + v1 * cs;
                    v0 = r1; v1 = r2;
                    if (z == 0) { v0 *= SCALE; v1 *= SCALE; }
                }
                size_t dst = (((size_t)(b * 16 + h) << 11) + s) * 128 + dk;
                if (z == 0) {
                    uint32_t hi, lo;
                    split_pair(v0, v1, hi, lo);
                    *(uint32_t*)(HI + dst)   = hi;
                    *(uint32_t*)(g_Ql + dst) = lo;
                } else {
                    *(uint32_t*)(HI + dst) = pack_f16x2(v0, v1);
                }
            }
        }
    }
}

// ===========================================================================
// Final GEMM: out = AO' * WO'^T, plain fp32 epilogue
// ===========================================================================
__global__ __launch_bounds__(256, 2)
void gemm_out(const __half* __restrict__ A, const __half* __restrict__ B,
              float* __restrict__ C)
{
    float c[4][4][4];
    gemm_mainloop(A, B, c);

    const int lane = threadIdx.x & 31, wid = threadIdx.x >> 5;
    const int bm = blockIdx.y * 128, bn = blockIdx.x * 128;
    const int wm = (wid >> 2) * 64, wn = (wid & 3) * 32;
    const int r0 = bm + wm + (lane >> 2);
    const int c0 = bn + wn + (lane & 3) * 2;
#pragma unroll
    for (int mt = 0; mt < 4; mt++)
#pragma unroll
        for (int nt = 0; nt < 4; nt++) {
            int rr = r0 + mt * 16, cc = c0 + nt * 8;
            *(float2*)(C + (size_t)rr * Dm + cc)       = make_float2(c[mt][nt][0], c[mt][nt][1]);
            *(float2*)(C + (size_t)(rr + 8) * Dm + cc) = make_float2(c[mt][nt][2], c[mt][nt][3]);
        }
}

// ===========================================================================
// Tensor-core flash attention, fp16 two-term, causal. (round-9 shape)
// BQ=BKV=64, 128 threads, 3 CTA/SM. K and V in SEPARATE commit groups:
// V load overlaps the QK passes + softmax of the same tile.
// ===========================================================================
#define FPB 272
#define TILEB ((uint32_t)(64 * FPB))   // 17408 bytes

__global__ __launch_bounds__(128, 3)
void flash_f16(const __half* __restrict__ Qh, const __half* __restrict__ Ql,
               const __half* __restrict__ Kh, const __half* __restrict__ Vh,
               __half* __restrict__ AO)
{
    extern __shared__ __align__(128) __half fsm[];
    const uint32_t sb = smem_to_u32(fsm);
    const uint32_t uQh = sb,            uQl = sb + TILEB;
    const uint32_t uKh = sb + 2*TILEB,  uVh = sb + 3*TILEB;

    const int tid = threadIdx.x, lane = tid & 31, wid = tid >> 5;
    const int qt = (int)gridDim.x - 1 - (int)blockIdx.x;
    const int bh = blockIdx.y;
    const int q0 = qt * 64;
    const size_t hbase = (size_t)bh * (2048 * 128);

#pragma unroll
    for (int i = 0; i < 8; i++) {
        int cc = tid + i * 128, row = cc >> 4, seg = cc & 15;
        uint32_t d = (uint32_t)(row * FPB + seg * 16);
        size_t g = hbase + (size_t)(q0 + row) * 128 + seg * 8;
        cpa16(uQh + d, Qh + g);
        cpa16(uQl + d, Ql + g);
    }
    asm volatile("cp.async.commit_group;" ::: "memory");

#define KFILL(jj) do {                                                         \
        int _c0 = (jj) * 64;                                                   \
        _Pragma("unroll")                                                      \
        for (int _i = 0; _i < 8; _i++) {                                       \
            int _cc = tid + _i * 128, _row = _cc >> 4, _seg = _cc & 15;        \
            uint32_t _d = (uint32_t)(_row * FPB + _seg * 16);                  \
            cpa16(uKh + _d, Kh + hbase + (size_t)(_c0 + _row) * 128 + _seg * 8); \
        }                                                                      \
        asm volatile("cp.async.commit_group;" ::: "memory");                   \
    } while (0)
#define VFILL(jj) do {                                                         \
        int _c0 = (jj) * 64;                                                   \
        _Pragma("unroll")                                                      \
        for (int _i = 0; _i < 8; _i++) {                                       \
            int _cc = tid + _i * 128, _row = _cc >> 4, _seg = _cc & 15;        \
            uint32_t _d = (uint32_t)(_row * FPB + _seg * 16);                  \
            cpa16(uVh + _d, Vh + hbase + (size_t)(_c0 + _row) * 128 + _seg * 8); \
        }                                                                      \
        asm volatile("cp.async.commit_group;" ::: "memory");                   \
    } while (0)

    KFILL(0); VFILL(0);

    float co[16][4];
#pragma unroll
    for (int i = 0; i < 16; i++)
#pragma unroll
        for (int k = 0; k < 4; k++) co[i][k] = 0.f;
    float m0v = -1e30f, m1v = -1e30f, l0v = 0.f, l1v = 0.f;

    const uint32_t aoff  = (uint32_t)((wid * 16 + (lane & 15)) * FPB + ((lane >> 4) << 4));
    const uint32_t bKoff = (uint32_t)(((lane & 7) + ((lane >> 4) << 3)) * FPB + (((lane >> 3) & 1) << 4));
    const uint32_t vloff = (uint32_t)((lane & 15) * FPB + ((lane >> 4) << 4));

    for (int j = 0; j <= qt; j++) {
        // K for tile j ready (V may still be in flight)
        asm volatile("cp.async.wait_group 1;" ::: "memory");
        __syncthreads();

        float cs[8][4];
#pragma unroll
        for (int i = 0; i < 8; i++)
#pragma unroll
            for (int k = 0; k < 4; k++) cs[i][k] = 0.f;

#pragma unroll
        for (int ks = 0; ks < 8; ks++) {
            uint32_t aH[4], aL[4];
            LDSM4(aH, uQh + aoff + ks * 32);
            LDSM4(aL, uQl + aoff + ks * 32);
#pragma unroll
            for (int np = 0; np < 4; np++) {
                uint32_t bH[4];
                uint32_t bo = bKoff + (uint32_t)(np * 16 * FPB) + ks * 32;
                LDSM4(bH, uKh + bo);
                MMA16816(cs[2*np],   aH, bH[0], bH[1]);
                MMA16816(cs[2*np+1], aH, bH[2], bH[3]);
                MMA16816(cs[2*np],   aL, bH[0], bH[1]);
                MMA16816(cs[2*np+1], aL, bH[2], bH[3]);
            }
        }

        if (j == qt) {
            int g = lane >> 2, t2 = (lane & 3) * 2;
            int r0 = wid * 16 + g, r1 = r0 + 8;
#pragma unroll
            for (int nt = 0; nt < 8; nt++) {
                int cl = nt * 8 + t2;
                if (cl     > r0) cs[nt][0] = -1e30f;
                if (cl + 1 > r0) cs[nt][1] = -1e30f;
                if (cl     > r1) cs[nt][2] = -1e30f;
                if (cl + 1 > r1) cs[nt][3] = -1e30f;
            }
        }

        float mx0 = -1e30f, mx1 = -1e30f;
#pragma unroll
        for (int nt = 0; nt < 8; nt++) {
            mx0 = fmaxf(mx0, fmaxf(cs[nt][0], cs[nt][1]));
            mx1 = fmaxf(mx1, fmaxf(cs[nt][2], cs[nt][3]));
        }
        mx0 = fmaxf(mx0, __shfl_xor_sync(0xffffffffu, mx0, 1));
        mx0 = fmaxf(mx0, __shfl_xor_sync(0xffffffffu, mx0, 2));
        mx1 = fmaxf(mx1, __shfl_xor_sync(0xffffffffu, mx1, 1));
        mx1 = fmaxf(mx1, __shfl_xor_sync(0xffffffffu, mx1, 2));
        float mn0 = fmaxf(m0v, mx0), mn1 = fmaxf(m1v, mx1);
        float al0 = __expf(m0v - mn0), al1 = __expf(m1v - mn1);
        m0v = mn0; m1v = mn1;
        float rs0 = 0.f, rs1 = 0.f;
#pragma unroll
        for (int nt = 0; nt < 8; nt++) {
            cs[nt][0] = __expf(cs[nt][0] - mn0);
            cs[nt][1] = __expf(cs[nt][1] - mn0);
            cs[nt][2] = __expf(cs[nt][2] - mn1);
            cs[nt][3] = __expf(cs[nt][3] - mn1);
            rs0 += cs[nt][0] + cs[nt][1];
            rs1 += cs[nt][2] + cs[nt][3];
        }
        rs0 += __shfl_xor_sync(0xffffffffu, rs0, 1);
        rs0 += __shfl_xor_sync(0xffffffffu, rs0, 2);
        rs1 += __shfl_xor_sync(0xffffffffu, rs1, 1);
        rs1 += __shfl_xor_sync(0xffffffffu, rs1, 2);
        l0v = l0v * al0 + rs0;
        l1v = l1v * al1 + rs1;
#pragma unroll
        for (int nt = 0; nt < 16; nt++) {
            co[nt][0] *= al0; co[nt][1] *= al0;
            co[nt][2] *= al1; co[nt][3] *= al1;
        }

        // V for tile j now required
        asm volatile("cp.async.wait_group 0;" ::: "memory");
        __syncthreads();

#pragma unroll
        for (int ks = 0; ks < 4; ks++) {
            float p0 = cs[2*ks][0],   p1 = cs[2*ks][1],   p2 = cs[2*ks][2],   p3 = cs[2*ks][3];
            float p4 = cs[2*ks+1][0], p5 = cs[2*ks+1][1], p6 = cs[2*ks+1][2], p7 = cs[2*ks+1][3];
            uint32_t aPh[4] = { pack_f16x2(p0, p1), pack_f16x2(p2, p3),
                                pack_f16x2(p4, p5), pack_f16x2(p6, p7) };
            uint32_t aPl[4] = {
                pack_f16x2(p0 - f16rt(p0), p1 - f16rt(p1)),
                pack_f16x2(p2 - f16rt(p2), p3 - f16rt(p3)),
                pack_f16x2(p4 - f16rt(p4), p5 - f16rt(p5)),
                pack_f16x2(p6 - f16rt(p6), p7 - f16rt(p7)) };
            uint32_t vb = vloff + (uint32_t)(ks * 16 * FPB);
#pragma unroll
            for (int dc = 0; dc < 8; dc++) {
                uint32_t vH[4];
                LDSM4T(vH, uVh + vb + dc * 32);
                MMA16816(co[2*dc],   aPh, vH[0], vH[1]);
                MMA16816(co[2*dc+1], aPh, vH[2], vH[3]);
                MMA16816(co[2*dc],   aPl, vH[0], vH[1]);
                MMA16816(co[2*dc+1], aPl, vH[2], vH[3]);
            }
        }

        __syncthreads();
        if (j < qt) { KFILL(j + 1); VFILL(j + 1); }
    }
#undef KFILL
#undef VFILL

    // ---- epilogue: write AO' packed [hi|lo] fp16 directly ----
    float i0 = 1.f / l0v, i1 = 1.f / l1v;
    const int b = bh >> 4, h = bh & 15;
    int g = lane >> 2, t2 = (lane & 3) * 2;
    const int r0 = b * 2048 + q0 + wid * 16 + g;
    const int cbase = h * 128 + t2;
#pragma unroll
    for (int nt = 0; nt < 16; nt++) {
        const int cc = cbase + nt * 8;
        uint32_t hi0, lo0, hi1, lo1;
        split_pair(co[nt][0] * i0, co[nt][1] * i0, hi0, lo0);
        split_pair(co[nt][2] * i1, co[nt][3] * i1, hi1, lo1);
        __half* row0 = AO + (size_t)r0 * KP2 + cc;
        __half* row1 = AO + (size_t)(r0 + 8) * KP2 + cc;
        *(uint32_t*)(row0)        = hi0;
        *(uint32_t*)(row0 + 2048) = lo0;
        *(uint32_t*)(row1)        = hi1;
        *(uint32_t*)(row1 + 2048) = lo1;
    }
}

// ===========================================================================
extern "C" void kernel_launch(void* const* d_in, const int* in_sizes, int n_in,
                              void* d_out, int out_size)
{
    const float* x  = (const float*)d_in[0];
    const float* WQ = (const float*)d_in[1];
    const float* WK = (const float*)d_in[2];
    const float* WV = (const float*)d_in[3];
    const float* WO = (const float*)d_in[4];
    const int*  pos = (const int*)d_in[5];
    float* out = (float*)d_out;

    __half *Axp, *Aaop, *Wqp, *Wkp, *Wvp, *Wop;
    __half *Qhp, *Qlp, *Khp, *Vhp;
    cudaGetSymbolAddress((void**)&Axp, g_Ax);
    cudaGetSymbolAddress((void**)&Aaop, g_Aao);
    cudaGetSymbolAddress((void**)&Wqp, g_Wq);
    cudaGetSymbolAddress((void**)&Wkp, g_Wk);
    cudaGetSymbolAddress((void**)&Wvp, g_Wv);
    cudaGetSymbolAddress((void**)&Wop, g_Wo);
    cudaGetSymbolAddress((void**)&Qhp, g_Qh);
    cudaGetSymbolAddress((void**)&Qlp, g_Ql);
    cudaGetSymbolAddress((void**)&Khp, g_Kh);
    cudaGetSymbolAddress((void**)&Vhp, g_Vh);

    prep<<<8192 + 4 * 4096, 256>>>(x, WQ, WK, WV, WO, Axp, Wqp, Wkp, Wvp, Wop);

    cudaFuncSetAttribute(gemm_qkv_fused, cudaFuncAttributeMaxDynamicSharedMemorySize, GSMEM);
    cudaFuncSetAttribute(gemm_out,       cudaFuncAttributeMaxDynamicSharedMemorySize, GSMEM);

    gemm_qkv_fused<<<dim3(Dm / 128, Mrows / 128, 3), 256, GSMEM>>>(Axp, Wqp, Wkp, Wvp, pos);

    cudaFuncSetAttribute(flash_f16, cudaFuncAttributeMaxDynamicSharedMemorySize, 4 * 17408);
    flash_f16<<<dim3(Sseq / 64, Bb * Hh), 128, 4 * 17408>>>(Qhp, Qlp, Khp, Vhp, Aaop);

    gemm_out<<<dim3(Dm / 128, Mrows / 128), 256, GSMEM>>>(Aaop, Wop, out);
}

// round 12
// speedup vs baseline: 1.3723x; 1.2976x over previous
#include <cuda_runtime.h>
#include <cuda_fp16.h>
#include <math.h>
#include <cstdint>

#define Dm   2048
#define Bb   2
#define Sseq 2048
#define Hh   16
#define DKk  128
#define Mrows 4096
#define KP2  4096          // 2 * 2048 (fp16 two-term split packed along K)
#define SCALE 0.08838834764831844055f  // 1/sqrt(128)

__device__ float g_invf[64];

// fp16 two-term split GEMM operands
__device__ __half g_Ax[(size_t)Mrows * KP2];    // [hi|lo]
__device__ __half g_Aao[(size_t)Mrows * 2048];  // hi only
__device__ __half g_Wq[(size_t)Dm * KP2];       // [hi|hi]
__device__ __half g_Wk[(size_t)Dm * KP2];
__device__ __half g_Wv[(size_t)Dm * KP2];
__device__ __half g_Wo[(size_t)Dm * KP2];

// per-head fp16 Q/K/V for flash:  [bh][s][128]
#define HS ((size_t)32 * 2048 * 128)
__device__ __half g_Qh[HS];
__device__ __half g_Ql[HS];
__device__ __half g_Kh[HS];
__device__ __half g_Vh[HS];

__device__ __forceinline__ uint32_t smem_to_u32(const void* p) {
    uint32_t a;
    asm("{ .reg .u64 t; cvta.to.shared.u64 t, %1; cvt.u32.u64 %0, t; }"
        : "=r"(a) : "l"(p));
    return a;
}
__device__ __forceinline__ void cpa16(uint32_t d, const void* g) {
    asm volatile("cp.async.cg.shared.global [%0], [%1], 16;" :: "r"(d), "l"(g) : "memory");
}
__device__ __forceinline__ uint32_t pack_f16x2(float lo, float hi) {
    uint32_t r;
    asm("cvt.rn.f16x2.f32 %0, %1, %2;" : "=r"(r) : "f"(hi), "f"(lo));
    return r;
}
__device__ __forceinline__ float f16rt(float x) {
    return __half2float(__float2half_rn(x));
}
__device__ __forceinline__ void split_pair(float v0, float v1, uint32_t& hi, uint32_t& lo) {
    hi = pack_f16x2(v0, v1);
    lo = pack_f16x2(v0 - f16rt(v0), v1 - f16rt(v1));
}

#define LDSM4(R, addr) \
    asm volatile("ldmatrix.sync.aligned.m8n8.x4.shared.b16 {%0,%1,%2,%3}, [%4];" \
        : "=r"((R)[0]), "=r"((R)[1]), "=r"((R)[2]), "=r"((R)[3]) : "r"(addr))
#define LDSM4T(R, addr) \
    asm volatile("ldmatrix.sync.aligned.m8n8.x4.trans.shared.b16 {%0,%1,%2,%3}, [%4];" \
        : "=r"((R)[0]), "=r"((R)[1]), "=r"((R)[2]), "=r"((R)[3]) : "r"(addr))
#define MMA16816(C, A, B0, B1) \
    asm volatile("mma.sync.aligned.m16n8k16.row.col.f32.f16.f16.f32 " \
        "{%0,%1,%2,%3}, {%4,%5,%6,%7}, {%8,%9}, {%0,%1,%2,%3};" \
        : "+f"((C)[0]), "+f"((C)[1]), "+f"((C)[2]), "+f"((C)[3]) \
        : "r"((A)[0]), "r"((A)[1]), "r"((A)[2]), "r"((A)[3]), "r"(B0), "r"(B1))

// ===========================================================================
// fp32 [R,2048] -> fp16 two-term packed [R,4096].
//   dup=0 (A operands): [hi|lo]   dup=1 (W operands): [hi|hi]
// ===========================================================================
__device__ __forceinline__
void conv_body(const float* __restrict__ X, __half* __restrict__ Y,
               int dup, int idx)
{
    int r  = idx >> 9;
    int c4 = idx & 511;
    float4 v = *(const float4*)(X + ((size_t)r << 11) + (c4 << 2));
    __half h0 = __float2half_rn(v.x), h1 = __float2half_rn(v.y);
    __half h2 = __float2half_rn(v.z), h3 = __float2half_rn(v.w);
    __half l0 = __float2half_rn(v.x - __half2float(h0));
    __half l1 = __float2half_rn(v.y - __half2float(h1));
    __half l2 = __float2half_rn(v.z - __half2float(h2));
    __half l3 = __float2half_rn(v.w - __half2float(h3));
    size_t row = (size_t)r * KP2;
    __half2 hA = __halves2half2(h0, h1), hB = __halves2half2(h2, h3);
    __half2 lA = __halves2half2(l0, l1), lB = __halves2half2(l2, l3);
    __half2* p0 = (__half2*)(Y + row + (c4 << 2));
    __half2* p1 = (__half2*)(Y + row + 2048 + (c4 << 2));
    p0[0] = hA; p0[1] = hB;
    if (dup) { p1[0] = hA; p1[1] = hB; }
    else     { p1[0] = lA; p1[1] = lB; }
}

// One launch: RoPE freqs + x split + 4 weight splits.
__global__ __launch_bounds__(256)
void prep(const float* __restrict__ x,
          const float* __restrict__ W0, const float* __restrict__ W1,
          const float* __restrict__ W2, const float* __restrict__ W3,
          __half* __restrict__ Yx,
          __half* __restrict__ Y0, __half* __restrict__ Y1,
          __half* __restrict__ Y2, __half* __restrict__ Y3)
{
    int bid = blockIdx.x, tid = threadIdx.x;
    if (bid == 0 && tid < 64)
        g_invf[tid] = (float)pow(10000.0, -(double)tid / 64.0);

    if (bid < 8192) {
        conv_body(x, Yx, 0, bid * 256 + tid);
    } else {
        int w   = (bid - 8192) >> 12;            // 0..3
        int sub = (bid - 8192) & 4095;
        const float* W = (w == 0) ? W0 : (w == 1) ? W1 : (w == 2) ? W2 : W3;
        __half*      Y = (w == 0) ? Y0 : (w == 1) ? Y1 : (w == 2) ? Y2 : Y3;
        conv_body(W, Y, 1, sub * 256 + tid);
    }
}

// ===========================================================================
// GEMM mainloop: CTA 128x128, BK=64 (pitch 144B), 3-stage cp.async,
// 8 warps (2x4), warp 64x32. Parameterized K-slab count + operand strides.
// ===========================================================================
#define SPITCH 144u
#define STG_OP (128u * SPITCH)          // 18432 B per operand per stage
#define STG_BOTH (2u * STG_OP)          // 36864 per stage
#define GSMEM (3u * STG_BOTH)           // 110592 total

__device__ __forceinline__
void gemm_mainloop(const __half* __restrict__ A,
                   const __half* __restrict__ B,
                   float c[4][4][4], int ktn, size_t strA, size_t strB)
{
    extern __shared__ __align__(128) char gsm[];
    const uint32_t sbase = smem_to_u32(gsm);
    const int tid = threadIdx.x;
    const int lane = tid & 31, wid = tid >> 5;
    const int bm = blockIdx.y * 128, bn = blockIdx.x * 128;
    const int wm = (wid >> 2) * 64, wn = (wid & 3) * 32;

    const __half* Ag = A + (size_t)bm * strA;
    const __half* Bg = B + (size_t)bn * strB;

#pragma unroll
    for (int i = 0; i < 4; i++)
#pragma unroll
        for (int j = 0; j < 4; j++)
#pragma unroll
            for (int k = 0; k < 4; k++) c[i][j][k] = 0.f;

    const int frow = tid >> 3;          // 0..31 (+32*j)
    const int fseg = tid & 7;           // 0..7

#define GFILL(s) do {                                                         \
        uint32_t _st = sbase + (uint32_t)((s) % 3) * STG_BOTH;                \
        int _ks = (s) * 64;                                                   \
        _Pragma("unroll")                                                     \
        for (int _j = 0; _j < 4; _j++) {                                      \
            int _row = frow + _j * 32;                                        \
            uint32_t _d = (uint32_t)(_row * SPITCH + fseg * 16);              \
            const void* _ga = Ag + (size_t)_row * strA + _ks + fseg * 8;      \
            const void* _gb = Bg + (size_t)_row * strB + _ks + fseg * 8;      \
            cpa16(_st + _d, _ga); cpa16(_st + STG_OP + _d, _gb);              \
        }                                                                     \
        asm volatile("cp.async.commit_group;" ::: "memory");                  \
    } while (0)

    GFILL(0); GFILL(1);

    const uint32_t aRowOff = (uint32_t)((wm + (lane & 15)) * SPITCH);
    const uint32_t bRowOff = (uint32_t)((wn + (lane & 7) + ((lane >> 4) << 3)) * SPITCH);
    const uint32_t aColOff = (uint32_t)((lane >> 4) << 4);
    const uint32_t bColOff = (uint32_t)(((lane >> 3) & 1) << 4);

    for (int kt = 0; kt < ktn; kt++) {
        asm volatile("cp.async.wait_group 1;" ::: "memory");
        __syncthreads();
        if (kt + 2 < ktn) { GFILL(kt + 2); }
        else { asm volatile("cp.async.commit_group;" ::: "memory"); }

        const uint32_t st = sbase + (uint32_t)(kt % 3) * STG_BOTH;
        const uint32_t sa = st, sb = st + STG_OP;

#pragma unroll
        for (int ks = 0; ks < 4; ks++) {
            uint32_t a[4][4], bf[2][4];
            const uint32_t ac = ks * 32 + aColOff;
            const uint32_t bc = ks * 32 + bColOff;
#pragma unroll
            for (int mt = 0; mt < 4; mt++)
                LDSM4(a[mt], sa + aRowOff + (uint32_t)(mt * 16) * SPITCH + ac);
#pragma unroll
            for (int nt2 = 0; nt2 < 2; nt2++)
                LDSM4(bf[nt2], sb + bRowOff + (uint32_t)(nt2 * 16) * SPITCH + bc);
#pragma unroll
            for (int mt = 0; mt < 4; mt++)
#pragma unroll
                for (int nt = 0; nt < 4; nt++)
                    MMA16816(c[mt][nt], a[mt],
                             bf[nt >> 1][(nt & 1) * 2], bf[nt >> 1][(nt & 1) * 2 + 1]);
        }
    }
#undef GFILL
}

// ===========================================================================
// QKV GEMM with fused RoPE + scale + fp16-split epilogue.
// z=0: Q (hi+lo out, K'=4096);  z=1: K (hi out, K'=4096);
// z=2: V (hi out, K'=2048 — hi-only mainloop, reads first halves).
// ===========================================================================
__global__ __launch_bounds__(256, 2)
void gemm_qkv_fused(const __half* __restrict__ A,
                    const __half* __restrict__ WQ, const __half* __restrict__ WK,
                    const __half* __restrict__ WV,
                    const int* __restrict__ pos)
{
    const int z = blockIdx.z;
    const __half* Bw = (z == 0) ? WQ : (z == 1) ? WK : WV;
    const int ktn = (z == 2) ? 32 : 64;

    float c[4][4][4];
    gemm_mainloop(A, Bw, c, ktn, KP2, KP2);

    __half* HI = (z == 0) ? g_Qh : (z == 1) ? g_Kh : g_Vh;

    const int lane = threadIdx.x & 31, wid = threadIdx.x >> 5;
    const int bm = blockIdx.y * 128, bn = blockIdx.x * 128;
    const int wm = (wid >> 2) * 64, wn = (wid & 3) * 32;
    const int r0 = bm + wm + (lane >> 2);
    const int c0 = bn + wn + (lane & 3) * 2;

#pragma unroll
    for (int mt = 0; mt < 4; mt++) {
#pragma unroll
        for (int half = 0; half < 2; half++) {
            const int rr = r0 + mt * 16 + half * 8;
            const int b = rr >> 11, s = rr & 2047;
            const int p = pos[s];
#pragma unroll
            for (int nt = 0; nt < 4; nt++) {
                const int cc = c0 + nt * 8;
                const int h = cc >> 7, dk = cc & 127;
                float v0 = c[mt][nt][half * 2], v1 = c[mt][nt][half * 2 + 1];
                if (z < 2) {
                    const int i = dk >> 1;
                    float ang = (float)p * g_invf[i];
                    float sn, cs;
                    sincosf(ang, &sn, &cs);
                    float r1 = v0 * cs - v1 * sn;
                    float r2 = v0 * sn + v1 * cs;
                    v0 = r1; v1 = r2;
                    if (z == 0) { v0 *= SCALE; v1 *= SCALE; }
                }
                size_t dst = (((size_t)(b * 16 + h) << 11) + s) * 128 + dk;
                if (z == 0) {
                    uint32_t hi, lo;
                    split_pair(v0, v1, hi, lo);
                    *(uint32_t*)(HI + dst)   = hi;
                    *(uint32_t*)(g_Ql + dst) = lo;
                } else {
                    *(uint32_t*)(HI + dst) = pack_f16x2(v0, v1);
                }
            }
        }
    }
}

// ===========================================================================
// Final GEMM: out = AOhi * Wohi^T (K'=2048), plain fp32 epilogue
// ===========================================================================
__global__ __launch_bounds__(256, 2)
void gemm_out(const __half* __restrict__ A, const __half* __restrict__ B,
              float* __restrict__ C)
{
    float c[4][4][4];
    gemm_mainloop(A, B, c, 32, 2048, KP2);

    const int lane = threadIdx.x & 31, wid = threadIdx.x >> 5;
    const int bm = blockIdx.y * 128, bn = blockIdx.x * 128;
    const int wm = (wid >> 2) * 64, wn = (wid & 3) * 32;
    const int r0 = bm + wm + (lane >> 2);
    const int c0 = bn + wn + (lane & 3) * 2;
#pragma unroll
    for (int mt = 0; mt < 4; mt++)
#pragma unroll
        for (int nt = 0; nt < 4; nt++) {
            int rr = r0 + mt * 16, cc = c0 + nt * 8;
            *(float2*)(C + (size_t)rr * Dm + cc)       = make_float2(c[mt][nt][0], c[mt][nt][1]);
            *(float2*)(C + (size_t)(rr + 8) * Dm + cc) = make_float2(c[mt][nt][2], c[mt][nt][3]);
        }
}

// ===========================================================================
// Tensor-core flash attention, fp16 two-term, causal.
// BQ=BKV=64, 128 threads, 3 CTA/SM. K/V in separate commit groups (R11).
// Epilogue writes AO hi-only (stride 2048).
// ===========================================================================
#define FPB 272
#define TILEB ((uint32_t)(64 * FPB))   // 17408 bytes

__global__ __launch_bounds__(128, 3)
void flash_f16(const __half* __restrict__ Qh, const __half* __restrict__ Ql,
               const __half* __restrict__ Kh, const __half* __restrict__ Vh,
               __half* __restrict__ AO)
{
    extern __shared__ __align__(128) __half fsm[];
    const uint32_t sb = smem_to_u32(fsm);
    const uint32_t uQh = sb,            uQl = sb + TILEB;
    const uint32_t uKh = sb + 2*TILEB,  uVh = sb + 3*TILEB;

    const int tid = threadIdx.x, lane = tid & 31, wid = tid >> 5;
    const int qt = (int)gridDim.x - 1 - (int)blockIdx.x;
    const int bh = blockIdx.y;
    const int q0 = qt * 64;
    const size_t hbase = (size_t)bh * (2048 * 128);

#pragma unroll
    for (int i = 0; i < 8; i++) {
        int cc = tid + i * 128, row = cc >> 4, seg = cc & 15;
        uint32_t d = (uint32_t)(row * FPB + seg * 16);
        size_t g = hbase + (size_t)(q0 + row) * 128 + seg * 8;
        cpa16(uQh + d, Qh + g);
        cpa16(uQl + d, Ql + g);
    }
    asm volatile("cp.async.commit_group;" ::: "memory");

#define KFILL(jj) do {                                                         \
        int _c0 = (jj) * 64;                                                   \
        _Pragma("unroll")                                                      \
        for (int _i = 0; _i < 8; _i++) {                                       \
            int _cc = tid + _i * 128, _row = _cc >> 4, _seg = _cc & 15;        \
            uint32_t _d = (uint32_t)(_row * FPB + _seg * 16);                  \
            cpa16(uKh + _d, Kh + hbase + (size_t)(_c0 + _row) * 128 + _seg * 8); \
        }                                                                      \
        asm volatile("cp.async.commit_group;" ::: "memory");                   \
    } while (0)
#define VFILL(jj) do {                                                         \
        int _c0 = (jj) * 64;                                                   \
        _Pragma("unroll")                                                      \
        for (int _i = 0; _i < 8; _i++) {                                       \
            int _cc = tid + _i * 128, _row = _cc >> 4, _seg = _cc & 15;        \
            uint32_t _d = (uint32_t)(_row * FPB + _seg * 16);                  \
            cpa16(uVh + _d, Vh + hbase + (size_t)(_c0 + _row) * 128 + _seg * 8); \
        }                                                                      \
        asm volatile("cp.async.commit_group;" ::: "memory");                   \
    } while (0)

    KFILL(0); VFILL(0);

    float co[16][4];
#pragma unroll
    for (int i = 0; i < 16; i++)
#pragma unroll
        for (int k = 0; k < 4; k++) co[i][k] = 0.f;
    float m0v = -1e30f, m1v = -1e30f, l0v = 0.f, l1v = 0.f;

    const uint32_t aoff  = (uint32_t)((wid * 16 + (lane & 15)) * FPB + ((lane >> 4) << 4));
    const uint32_t bKoff = (uint32_t)(((lane & 7) + ((lane >> 4) << 3)) * FPB + (((lane >> 3) & 1) << 4));
    const uint32_t vloff = (uint32_t)((lane & 15) * FPB + ((lane >> 4) << 4));

    for (int j = 0; j <= qt; j++) {
        asm volatile("cp.async.wait_group 1;" ::: "memory");
        __syncthreads();

        float cs[8][4];
#pragma unroll
        for (int i = 0; i < 8; i++)
#pragma unroll
            for (int k = 0; k < 4; k++) cs[i][k] = 0.f;

#pragma unroll
        for (int ks = 0; ks < 8; ks++) {
            uint32_t aH[4], aL[4];
            LDSM4(aH, uQh + aoff + ks * 32);
            LDSM4(aL, uQl + aoff + ks * 32);
#pragma unroll
            for (int np = 0; np < 4; np++) {
                uint32_t bH[4];
                uint32_t bo = bKoff + (uint32_t)(np * 16 * FPB) + ks * 32;
                LDSM4(bH, uKh + bo);
                MMA16816(cs[2*np],   aH, bH[0], bH[1]);
                MMA16816(cs[2*np+1], aH, bH[2], bH[3]);
                MMA16816(cs[2*np],   aL, bH[0], bH[1]);
                MMA16816(cs[2*np+1], aL, bH[2], bH[3]);
            }
        }

        if (j == qt) {
            int g = lane >> 2, t2 = (lane & 3) * 2;
            int r0 = wid * 16 + g, r1 = r0 + 8;
#pragma unroll
            for (int nt = 0; nt < 8; nt++) {
                int cl = nt * 8 + t2;
                if (cl     > r0) cs[nt][0] = -1e30f;
                if (cl + 1 > r0) cs[nt][1] = -1e30f;
                if (cl     > r1) cs[nt][2] = -1e30f;
                if (cl + 1 > r1) cs[nt][3] = -1e30f;
            }
        }

        float mx0 = -1e30f, mx1 = -1e30f;
#pragma unroll
        for (int nt = 0; nt < 8; nt++) {
            mx0 = fmaxf(mx0, fmaxf(cs[nt][0], cs[nt][1]));
            mx1 = fmaxf(mx1, fmaxf(cs[nt][2], cs[nt][3]));
        }
        mx0 = fmaxf(mx0, __shfl_xor_sync(0xffffffffu, mx0, 1));
        mx0 = fmaxf(mx0, __shfl_xor_sync(0xffffffffu, mx0, 2));
        mx1 = fmaxf(mx1, __shfl_xor_sync(0xffffffffu, mx1, 1));
        mx1 = fmaxf(mx1, __shfl_xor_sync(0xffffffffu, mx1, 2));
        float mn0 = fmaxf(m0v, mx0), mn1 = fmaxf(m1v, mx1);
        float al0 = __expf(m0v - mn0), al1 = __expf(m1v - mn1);
        m0v = mn0; m1v = mn1;
        float rs0 = 0.f, rs1 = 0.f;
#pragma unroll
        for (int nt = 0; nt < 8; nt++) {
            cs[nt][0] = __expf(cs[nt][0] - mn0);
            cs[nt][1] = __expf(cs[nt][1] - mn0);
            cs[nt][2] = __expf(cs[nt][2] - mn1);
            cs[nt][3] = __expf(cs[nt][3] - mn1);
            rs0 += cs[nt][0] + cs[nt][1];
            rs1 += cs[nt][2] + cs[nt][3];
        }
        rs0 += __shfl_xor_sync(0xffffffffu, rs0, 1);
        rs0 += __shfl_xor_sync(0xffffffffu, rs0, 2);
        rs1 += __shfl_xor_sync(0xffffffffu, rs1, 1);
        rs1 += __shfl_xor_sync(0xffffffffu, rs1, 2);
        l0v = l0v * al0 + rs0;
        l1v = l1v * al1 + rs1;
#pragma unroll
        for (int nt = 0; nt < 16; nt++) {
            co[nt][0] *= al0; co[nt][1] *= al0;
            co[nt][2] *= al1; co[nt][3] *= al1;
        }

        asm volatile("cp.async.wait_group 0;" ::: "memory");
        __syncthreads();

#pragma unroll
        for (int ks = 0; ks < 4; ks++) {
            float p0 = cs[2*ks][0],   p1 = cs[2*ks][1],   p2 = cs[2*ks][2],   p3 = cs[2*ks][3];
            float p4 = cs[2*ks+1][0], p5 = cs[2*ks+1][1], p6 = cs[2*ks+1][2], p7 = cs[2*ks+1][3];
            uint32_t aPh[4] = { pack_f16x2(p0, p1), pack_f16x2(p2, p3),
                                pack_f16x2(p4, p5), pack_f16x2(p6, p7) };
            uint32_t aPl[4] = {
                pack_f16x2(p0 - f16rt(p0), p1 - f16rt(p1)),
                pack_f16x2(p2 - f16rt(p2), p3 - f16rt(p3)),
                pack_f16x2(p4 - f16rt(p4), p5 - f16rt(p5)),
                pack_f16x2(p6 - f16rt(p6), p7 - f16rt(p7)) };
            uint32_t vb = vloff + (uint32_t)(ks * 16 * FPB);
#pragma unroll
            for (int dc = 0; dc < 8; dc++) {
                uint32_t vH[4];
                LDSM4T(vH, uVh + vb + dc * 32);
                MMA16816(co[2*dc],   aPh, vH[0], vH[1]);
                MMA16816(co[2*dc+1], aPh, vH[2], vH[3]);
                MMA16816(co[2*dc],   aPl, vH[0], vH[1]);
                MMA16816(co[2*dc+1], aPl, vH[2], vH[3]);
            }
        }

        __syncthreads();
        if (j < qt) { KFILL(j + 1); VFILL(j + 1); }
    }
#undef KFILL
#undef VFILL

    // ---- epilogue: write AO hi-only fp16 (stride 2048) ----
    float i0 = 1.f / l0v, i1 = 1.f / l1v;
    const int b = bh >> 4, h = bh & 15;
    int g = lane >> 2, t2 = (lane & 3) * 2;
    const int r0 = b * 2048 + q0 + wid * 16 + g;
    const int cbase = h * 128 + t2;
#pragma unroll
    for (int nt = 0; nt < 16; nt++) {
        const int cc = cbase + nt * 8;
        *(uint32_t*)(AO + (size_t)r0 * 2048 + cc) =
            pack_f16x2(co[nt][0] * i0, co[nt][1] * i0);
        *(uint32_t*)(AO + (size_t)(r0 + 8) * 2048 + cc) =
            pack_f16x2(co[nt][2] * i1, co[nt][3] * i1);
    }
}

// ===========================================================================
extern "C" void kernel_launch(void* const* d_in, const int* in_sizes, int n_in,
                              void* d_out, int out_size)
{
    const float* x  = (const float*)d_in[0];
    const float* WQ = (const float*)d_in[1];
    const float* WK = (const float*)d_in[2];
    const float* WV = (const float*)d_in[3];
    const float* WO = (const float*)d_in[4];
    const int*  pos = (const int*)d_in[5];
    float* out = (float*)d_out;

    __half *Axp, *Aaop, *Wqp, *Wkp, *Wvp, *Wop;
    __half *Qhp, *Qlp, *Khp, *Vhp;
    cudaGetSymbolAddress((void**)&Axp, g_Ax);
    cudaGetSymbolAddress((void**)&Aaop, g_Aao);
    cudaGetSymbolAddress((void**)&Wqp, g_Wq);
    cudaGetSymbolAddress((void**)&Wkp, g_Wk);
    cudaGetSymbolAddress((void**)&Wvp, g_Wv);
    cudaGetSymbolAddress((void**)&Wop, g_Wo);
    cudaGetSymbolAddress((void**)&Qhp, g_Qh);
    cudaGetSymbolAddress((void**)&Qlp, g_Ql);
    cudaGetSymbolAddress((void**)&Khp, g_Kh);
    cudaGetSymbolAddress((void**)&Vhp, g_Vh);

    prep<<<8192 + 4 * 4096, 256>>>(x, WQ, WK, WV, WO, Axp, Wqp, Wkp, Wvp, Wop);

    cudaFuncSetAttribute(gemm_qkv_fused, cudaFuncAttributeMaxDynamicSharedMemorySize, GSMEM);
    cudaFuncSetAttribute(gemm_out,       cudaFuncAttributeMaxDynamicSharedMemorySize, GSMEM);

    gemm_qkv_fused<<<dim3(Dm / 128, Mrows / 128, 3), 256, GSMEM>>>(Axp, Wqp, Wkp, Wvp, pos);

    cudaFuncSetAttribute(flash_f16, cudaFuncAttributeMaxDynamicSharedMemorySize, 4 * 17408);
    flash_f16<<<dim3(Sseq / 64, Bb * Hh), 128, 4 * 17408>>>(Qhp, Qlp, Khp, Vhp, Aaop);

    gemm_out<<<dim3(Dm / 128, Mrows / 128), 256, GSMEM>>>(Aaop, Wop, out);
}

// round 13
// speedup vs baseline: 1.5044x; 1.0962x over previous
#include <cuda_runtime.h>
#include <cuda_fp16.h>
#include <math.h>
#include <cstdint>

#define Dm   2048
#define Bb   2
#define Sseq 2048
#define Hh   16
#define DKk  128
#define Mrows 4096
#define KP2  4096          // 2 * 2048 (fp16 two-term split packed along K)
#define SCALE 0.08838834764831844055f  // 1/sqrt(128)

__device__ float g_invf[64];

// fp16 two-term split GEMM operands
__device__ __half g_Ax[(size_t)Mrows * KP2];    // [hi|lo]
__device__ __half g_Aao[(size_t)Mrows * 2048];  // hi only
__device__ __half g_Wq[(size_t)Dm * KP2];       // [hi|hi]
__device__ __half g_Wk[(size_t)Dm * KP2];
__device__ __half g_Wv[(size_t)Dm * KP2];
__device__ __half g_Wo[(size_t)Dm * KP2];

// per-head fp16 Q/K/V for flash:  [bh][s][128]
#define HS ((size_t)32 * 2048 * 128)
__device__ __half g_Qh[HS];
__device__ __half g_Ql[HS];
__device__ __half g_Kh[HS];
__device__ __half g_Vh[HS];

__device__ __forceinline__ uint32_t smem_to_u32(const void* p) {
    uint32_t a;
    asm("{ .reg .u64 t; cvta.to.shared.u64 t, %1; cvt.u32.u64 %0, t; }"
        : "=r"(a) : "l"(p));
    return a;
}
__device__ __forceinline__ void cpa16(uint32_t d, const void* g) {
    asm volatile("cp.async.cg.shared.global [%0], [%1], 16;" :: "r"(d), "l"(g) : "memory");
}
__device__ __forceinline__ uint32_t pack_f16x2(float lo, float hi) {
    uint32_t r;
    asm("cvt.rn.f16x2.f32 %0, %1, %2;" : "=r"(r) : "f"(hi), "f"(lo));
    return r;
}
__device__ __forceinline__ float f16rt(float x) {
    return __half2float(__float2half_rn(x));
}
__device__ __forceinline__ void split_pair(float v0, float v1, uint32_t& hi, uint32_t& lo) {
    hi = pack_f16x2(v0, v1);
    lo = pack_f16x2(v0 - f16rt(v0), v1 - f16rt(v1));
}

#define LDSM4(R, addr) \
    asm volatile("ldmatrix.sync.aligned.m8n8.x4.shared.b16 {%0,%1,%2,%3}, [%4];" \
        : "=r"((R)[0]), "=r"((R)[1]), "=r"((R)[2]), "=r"((R)[3]) : "r"(addr))
#define LDSM4T(R, addr) \
    asm volatile("ldmatrix.sync.aligned.m8n8.x4.trans.shared.b16 {%0,%1,%2,%3}, [%4];" \
        : "=r"((R)[0]), "=r"((R)[1]), "=r"((R)[2]), "=r"((R)[3]) : "r"(addr))
#define MMA16816(C, A, B0, B1) \
    asm volatile("mma.sync.aligned.m16n8k16.row.col.f32.f16.f16.f32 " \
        "{%0,%1,%2,%3}, {%4,%5,%6,%7}, {%8,%9}, {%0,%1,%2,%3};" \
        : "+f"((C)[0]), "+f"((C)[1]), "+f"((C)[2]), "+f"((C)[3]) \
        : "r"((A)[0]), "r"((A)[1]), "r"((A)[2]), "r"((A)[3]), "r"(B0), "r"(B1))

// ===========================================================================
// fp32 [R,2048] -> fp16 two-term packed [R,4096].
//   dup=0 (A operands): [hi|lo]   dup=1 (W operands): [hi|hi]
// ===========================================================================
__device__ __forceinline__
void conv_body(const float* __restrict__ X, __half* __restrict__ Y,
               int dup, int idx)
{
    int r  = idx >> 9;
    int c4 = idx & 511;
    float4 v = *(const float4*)(X + ((size_t)r << 11) + (c4 << 2));
    __half h0 = __float2half_rn(v.x), h1 = __float2half_rn(v.y);
    __half h2 = __float2half_rn(v.z), h3 = __float2half_rn(v.w);
    __half l0 = __float2half_rn(v.x - __half2float(h0));
    __half l1 = __float2half_rn(v.y - __half2float(h1));
    __half l2 = __float2half_rn(v.z - __half2float(h2));
    __half l3 = __float2half_rn(v.w - __half2float(h3));
    size_t row = (size_t)r * KP2;
    __half2 hA = __halves2half2(h0, h1), hB = __halves2half2(h2, h3);
    __half2 lA = __halves2half2(l0, l1), lB = __halves2half2(l2, l3);
    __half2* p0 = (__half2*)(Y + row + (c4 << 2));
    __half2* p1 = (__half2*)(Y + row + 2048 + (c4 << 2));
    p0[0] = hA; p0[1] = hB;
    if (dup) { p1[0] = hA; p1[1] = hB; }
    else     { p1[0] = lA; p1[1] = lB; }
}

// One launch: RoPE freqs + x split + 4 weight splits.
__global__ __launch_bounds__(256)
void prep(const float* __restrict__ x,
          const float* __restrict__ W0, const float* __restrict__ W1,
          const float* __restrict__ W2, const float* __restrict__ W3,
          __half* __restrict__ Yx,
          __half* __restrict__ Y0, __half* __restrict__ Y1,
          __half* __restrict__ Y2, __half* __restrict__ Y3)
{
    int bid = blockIdx.x, tid = threadIdx.x;
    if (bid == 0 && tid < 64)
        g_invf[tid] = (float)pow(10000.0, -(double)tid / 64.0);

    if (bid < 8192) {
        conv_body(x, Yx, 0, bid * 256 + tid);
    } else {
        int w   = (bid - 8192) >> 12;            // 0..3
        int sub = (bid - 8192) & 4095;
        const float* W = (w == 0) ? W0 : (w == 1) ? W1 : (w == 2) ? W2 : W3;
        __half*      Y = (w == 0) ? Y0 : (w == 1) ? Y1 : (w == 2) ? Y2 : Y3;
        conv_body(W, Y, 1, sub * 256 + tid);
    }
}

// ===========================================================================
// GEMM mainloop: CTA 128x128, BK=64 (pitch 144B), 3-stage cp.async,
// 8 warps (2x4), warp 64x32. Parameterized K-slab count + operand strides.
// ===========================================================================
#define SPITCH 144u
#define STG_OP (128u * SPITCH)          // 18432 B per operand per stage
#define STG_BOTH (2u * STG_OP)          // 36864 per stage
#define GSMEM (3u * STG_BOTH)           // 110592 total

__device__ __forceinline__
void gemm_mainloop(const __half* __restrict__ A,
                   const __half* __restrict__ B,
                   float c[4][4][4], int ktn, size_t strA, size_t strB)
{
    extern __shared__ __align__(128) char gsm[];
    const uint32_t sbase = smem_to_u32(gsm);
    const int tid = threadIdx.x;
    const int lane = tid & 31, wid = tid >> 5;
    const int bm = blockIdx.y * 128, bn = blockIdx.x * 128;
    const int wm = (wid >> 2) * 64, wn = (wid & 3) * 32;

    const __half* Ag = A + (size_t)bm * strA;
    const __half* Bg = B + (size_t)bn * strB;

#pragma unroll
    for (int i = 0; i < 4; i++)
#pragma unroll
        for (int j = 0; j < 4; j++)
#pragma unroll
            for (int k = 0; k < 4; k++) c[i][j][k] = 0.f;

    const int frow = tid >> 3;          // 0..31 (+32*j)
    const int fseg = tid & 7;           // 0..7

#define GFILL(s) do {                                                         \
        uint32_t _st = sbase + (uint32_t)((s) % 3) * STG_BOTH;                \
        int _ks = (s) * 64;                                                   \
        _Pragma("unroll")                                                     \
        for (int _j = 0; _j < 4; _j++) {                                      \
            int _row = frow + _j * 32;                                        \
            uint32_t _d = (uint32_t)(_row * SPITCH + fseg * 16);              \
            const void* _ga = Ag + (size_t)_row * strA + _ks + fseg * 8;      \
            const void* _gb = Bg + (size_t)_row * strB + _ks + fseg * 8;      \
            cpa16(_st + _d, _ga); cpa16(_st + STG_OP + _d, _gb);              \
        }                                                                     \
        asm volatile("cp.async.commit_group;" ::: "memory");                  \
    } while (0)

    GFILL(0); GFILL(1);

    const uint32_t aRowOff = (uint32_t)((wm + (lane & 15)) * SPITCH);
    const uint32_t bRowOff = (uint32_t)((wn + (lane & 7) + ((lane >> 4) << 3)) * SPITCH);
    const uint32_t aColOff = (uint32_t)((lane >> 4) << 4);
    const uint32_t bColOff = (uint32_t)(((lane >> 3) & 1) << 4);

    for (int kt = 0; kt < ktn; kt++) {
        asm volatile("cp.async.wait_group 1;" ::: "memory");
        __syncthreads();
        if (kt + 2 < ktn) { GFILL(kt + 2); }
        else { asm volatile("cp.async.commit_group;" ::: "memory"); }

        const uint32_t st = sbase + (uint32_t)(kt % 3) * STG_BOTH;
        const uint32_t sa = st, sb = st + STG_OP;

#pragma unroll
        for (int ks = 0; ks < 4; ks++) {
            uint32_t a[4][4], bf[2][4];
            const uint32_t ac = ks * 32 + aColOff;
            const uint32_t bc = ks * 32 + bColOff;
#pragma unroll
            for (int mt = 0; mt < 4; mt++)
                LDSM4(a[mt], sa + aRowOff + (uint32_t)(mt * 16) * SPITCH + ac);
#pragma unroll
            for (int nt2 = 0; nt2 < 2; nt2++)
                LDSM4(bf[nt2], sb + bRowOff + (uint32_t)(nt2 * 16) * SPITCH + bc);
#pragma unroll
            for (int mt = 0; mt < 4; mt++)
#pragma unroll
                for (int nt = 0; nt < 4; nt++)
                    MMA16816(c[mt][nt], a[mt],
                             bf[nt >> 1][(nt & 1) * 2], bf[nt >> 1][(nt & 1) * 2 + 1]);
        }
    }
#undef GFILL
}

// ===========================================================================
// QKV GEMM with fused RoPE + scale + fp16-split epilogue.
// z=0: Q (hi+lo out, K'=4096 full two-term);
// z=1: K (hi out, K'=2048 hi-only);  z=2: V (hi out, K'=2048 hi-only).
// ===========================================================================
__global__ __launch_bounds__(256, 2)
void gemm_qkv_fused(const __half* __restrict__ A,
                    const __half* __restrict__ WQ, const __half* __restrict__ WK,
                    const __half* __restrict__ WV,
                    const int* __restrict__ pos)
{
    const int z = blockIdx.z;
    const __half* Bw = (z == 0) ? WQ : (z == 1) ? WK : WV;
    const int ktn = (z == 0) ? 64 : 32;

    float c[4][4][4];
    gemm_mainloop(A, Bw, c, ktn, KP2, KP2);

    __half* HI = (z == 0) ? g_Qh : (z == 1) ? g_Kh : g_Vh;

    const int lane = threadIdx.x & 31, wid = threadIdx.x >> 5;
    const int bm = blockIdx.y * 128, bn = blockIdx.x * 128;
    const int wm = (wid >> 2) * 64, wn = (wid & 3) * 32;
    const int r0 = bm + wm + (lane >> 2);
    const int c0 = bn + wn + (lane & 3) * 2;

#pragma unroll
    for (int mt = 0; mt < 4; mt++) {
#pragma unroll
        for (int half = 0; half < 2; half++) {
            const int rr = r0 + mt * 16 + half * 8;
            const int b = rr >> 11, s = rr & 2047;
            const int p = pos[s];
#pragma unroll
            for (int nt = 0; nt < 4; nt++) {
                const int cc = c0 + nt * 8;
                const int h = cc >> 7, dk = cc & 127;
                float v0 = c[mt][nt][half * 2], v1 = c[mt][nt][half * 2 + 1];
                if (z < 2) {
                    const int i = dk >> 1;
                    float ang = (float)p * g_invf[i];
                    float sn, cs;
                    sincosf(ang, &sn, &cs);
                    float r1 = v0 * cs - v1 * sn;
                    float r2 = v0 * sn + v1 * cs;
                    v0 = r1; v1 = r2;
                    if (z == 0) { v0 *= SCALE; v1 *= SCALE; }
                }
                size_t dst = (((size_t)(b * 16 + h) << 11) + s) * 128 + dk;
                if (z == 0) {
                    uint32_t hi, lo;
                    split_pair(v0, v1, hi, lo);
                    *(uint32_t*)(HI + dst)   = hi;
                    *(uint32_t*)(g_Ql + dst) = lo;
                } else {
                    *(uint32_t*)(HI + dst) = pack_f16x2(v0, v1);
                }
            }
        }
    }
}

// ===========================================================================
// Final GEMM: out = AOhi * Wohi^T (K'=2048), plain fp32 epilogue
// ===========================================================================
__global__ __launch_bounds__(256, 2)
void gemm_out(const __half* __restrict__ A, const __half* __restrict__ B,
              float* __restrict__ C)
{
    float c[4][4][4];
    gemm_mainloop(A, B, c, 32, 2048, KP2);

    const int lane = threadIdx.x & 31, wid = threadIdx.x >> 5;
    const int bm = blockIdx.y * 128, bn = blockIdx.x * 128;
    const int wm = (wid >> 2) * 64, wn = (wid & 3) * 32;
    const int r0 = bm + wm + (lane >> 2);
    const int c0 = bn + wn + (lane & 3) * 2;
#pragma unroll
    for (int mt = 0; mt < 4; mt++)
#pragma unroll
        for (int nt = 0; nt < 4; nt++) {
            int rr = r0 + mt * 16, cc = c0 + nt * 8;
            *(float2*)(C + (size_t)rr * Dm + cc)       = make_float2(c[mt][nt][0], c[mt][nt][1]);
            *(float2*)(C + (size_t)(rr + 8) * Dm + cc) = make_float2(c[mt][nt][2], c[mt][nt][3]);
        }
}

// ===========================================================================
// Tensor-core flash attention, fp16 two-term, causal.
// BQ=BKV=64, 128 threads, 3 CTA/SM. K/V in separate commit groups (R11).
// Epilogue writes AO hi-only (stride 2048).
// ===========================================================================
#define FPB 272
#define TILEB ((uint32_t)(64 * FPB))   // 17408 bytes

__global__ __launch_bounds__(128, 3)
void flash_f16(const __half* __restrict__ Qh, const __half* __restrict__ Ql,
               const __half* __restrict__ Kh, const __half* __restrict__ Vh,
               __half* __restrict__ AO)
{
    extern __shared__ __align__(128) __half fsm[];
    const uint32_t sb = smem_to_u32(fsm);
    const uint32_t uQh = sb,            uQl = sb + TILEB;
    const uint32_t uKh = sb + 2*TILEB,  uVh = sb + 3*TILEB;

    const int tid = threadIdx.x, lane = tid & 31, wid = tid >> 5;
    const int qt = (int)gridDim.x - 1 - (int)blockIdx.x;
    const int bh = blockIdx.y;
    const int q0 = qt * 64;
    const size_t hbase = (size_t)bh * (2048 * 128);

#pragma unroll
    for (int i = 0; i < 8; i++) {
        int cc = tid + i * 128, row = cc >> 4, seg = cc & 15;
        uint32_t d = (uint32_t)(row * FPB + seg * 16);
        size_t g = hbase + (size_t)(q0 + row) * 128 + seg * 8;
        cpa16(uQh + d, Qh + g);
        cpa16(uQl + d, Ql + g);
    }
    asm volatile("cp.async.commit_group;" ::: "memory");

#define KFILL(jj) do {                                                         \
        int _c0 = (jj) * 64;                                                   \
        _Pragma("unroll")                                                      \
        for (int _i = 0; _i < 8; _i++) {                                       \
            int _cc = tid + _i * 128, _row = _cc >> 4, _seg = _cc & 15;        \
            uint32_t _d = (uint32_t)(_row * FPB + _seg * 16);                  \
            cpa16(uKh + _d, Kh + hbase + (size_t)(_c0 + _row) * 128 + _seg * 8); \
        }                                                                      \
        asm volatile("cp.async.commit_group;" ::: "memory");                   \
    } while (0)
#define VFILL(jj) do {                                                         \
        int _c0 = (jj) * 64;                                                   \
        _Pragma("unroll")                                                      \
        for (int _i = 0; _i < 8; _i++) {                                       \
            int _cc = tid + _i * 128, _row = _cc >> 4, _seg = _cc & 15;        \
            uint32_t _d = (uint32_t)(_row * FPB + _seg * 16);                  \
            cpa16(uVh + _d, Vh + hbase + (size_t)(_c0 + _row) * 128 + _seg * 8); \
        }                                                                      \
        asm volatile("cp.async.commit_group;" ::: "memory");                   \
    } while (0)

    KFILL(0); VFILL(0);

    float co[16][4];
#pragma unroll
    for (int i = 0; i < 16; i++)
#pragma unroll
        for (int k = 0; k < 4; k++) co[i][k] = 0.f;
    float m0v = -1e30f, m1v = -1e30f, l0v = 0.f, l1v = 0.f;

    const uint32_t aoff  = (uint32_t)((wid * 16 + (lane & 15)) * FPB + ((lane >> 4) << 4));
    const uint32_t bKoff = (uint32_t)(((lane & 7) + ((lane >> 4) << 3)) * FPB + (((lane >> 3) & 1) << 4));
    const uint32_t vloff = (uint32_t)((lane & 15) * FPB + ((lane >> 4) << 4));

    for (int j = 0; j <= qt; j++) {
        asm volatile("cp.async.wait_group 1;" ::: "memory");
        __syncthreads();

        float cs[8][4];
#pragma unroll
        for (int i = 0; i < 8; i++)
#pragma unroll
            for (int k = 0; k < 4; k++) cs[i][k] = 0.f;

#pragma unroll
        for (int ks = 0; ks < 8; ks++) {
            uint32_t aH[4], aL[4];
            LDSM4(aH, uQh + aoff + ks * 32);
            LDSM4(aL, uQl + aoff + ks * 32);
#pragma unroll
            for (int np = 0; np < 4; np++) {
                uint32_t bH[4];
                uint32_t bo = bKoff + (uint32_t)(np * 16 * FPB) + ks * 32;
                LDSM4(bH, uKh + bo);
                MMA16816(cs[2*np],   aH, bH[0], bH[1]);
                MMA16816(cs[2*np+1], aH, bH[2], bH[3]);
                MMA16816(cs[2*np],   aL, bH[0], bH[1]);
                MMA16816(cs[2*np+1], aL, bH[2], bH[3]);
            }
        }

        if (j == qt) {
            int g = lane >> 2, t2 = (lane & 3) * 2;
            int r0 = wid * 16 + g, r1 = r0 + 8;
#pragma unroll
            for (int nt = 0; nt < 8; nt++) {
                int cl = nt * 8 + t2;
                if (cl     > r0) cs[nt][0] = -1e30f;
                if (cl + 1 > r0) cs[nt][1] = -1e30f;
                if (cl     > r1) cs[nt][2] = -1e30f;
                if (cl + 1 > r1) cs[nt][3] = -1e30f;
            }
        }

        float mx0 = -1e30f, mx1 = -1e30f;
#pragma unroll
        for (int nt = 0; nt < 8; nt++) {
            mx0 = fmaxf(mx0, fmaxf(cs[nt][0], cs[nt][1]));
            mx1 = fmaxf(mx1, fmaxf(cs[nt][2], cs[nt][3]));
        }
        mx0 = fmaxf(mx0, __shfl_xor_sync(0xffffffffu, mx0, 1));
        mx0 = fmaxf(mx0, __shfl_xor_sync(0xffffffffu, mx0, 2));
        mx1 = fmaxf(mx1, __shfl_xor_sync(0xffffffffu, mx1, 1));
        mx1 = fmaxf(mx1, __shfl_xor_sync(0xffffffffu, mx1, 2));
        float mn0 = fmaxf(m0v, mx0), mn1 = fmaxf(m1v, mx1);
        float al0 = __expf(m0v - mn0), al1 = __expf(m1v - mn1);
        m0v = mn0; m1v = mn1;
        float rs0 = 0.f, rs1 = 0.f;
#pragma unroll
        for (int nt = 0; nt < 8; nt++) {
            cs[nt][0] = __expf(cs[nt][0] - mn0);
            cs[nt][1] = __expf(cs[nt][1] - mn0);
            cs[nt][2] = __expf(cs[nt][2] - mn1);
            cs[nt][3] = __expf(cs[nt][3] - mn1);
            rs0 += cs[nt][0] + cs[nt][1];
            rs1 += cs[nt][2] + cs[nt][3];
        }
        rs0 += __shfl_xor_sync(0xffffffffu, rs0, 1);
        rs0 += __shfl_xor_sync(0xffffffffu, rs0, 2);
        rs1 += __shfl_xor_sync(0xffffffffu, rs1, 1);
        rs1 += __shfl_xor_sync(0xffffffffu, rs1, 2);
        l0v = l0v * al0 + rs0;
        l1v = l1v * al1 + rs1;
#pragma unroll
        for (int nt = 0; nt < 16; nt++) {
            co[nt][0] *= al0; co[nt][1] *= al0;
            co[nt][2] *= al1; co[nt][3] *= al1;
        }

        asm volatile("cp.async.wait_group 0;" ::: "memory");
        __syncthreads();

#pragma unroll
        for (int ks = 0; ks < 4; ks++) {
            float p0 = cs[2*ks][0],   p1 = cs[2*ks][1],   p2 = cs[2*ks][2],   p3 = cs[2*ks][3];
            float p4 = cs[2*ks+1][0], p5 = cs[2*ks+1][1], p6 = cs[2*ks+1][2], p7 = cs[2*ks+1][3];
            uint32_t aPh[4] = { pack_f16x2(p0, p1), pack_f16x2(p2, p3),
                                pack_f16x2(p4, p5), pack_f16x2(p6, p7) };
            uint32_t aPl[4] = {
                pack_f16x2(p0 - f16rt(p0), p1 - f16rt(p1)),
                pack_f16x2(p2 - f16rt(p2), p3 - f16rt(p3)),
                pack_f16x2(p4 - f16rt(p4), p5 - f16rt(p5)),
                pack_f16x2(p6 - f16rt(p6), p7 - f16rt(p7)) };
            uint32_t vb = vloff + (uint32_t)(ks * 16 * FPB);
#pragma unroll
            for (int dc = 0; dc < 8; dc++) {
                uint32_t vH[4];
                LDSM4T(vH, uVh + vb + dc * 32);
                MMA16816(co[2*dc],   aPh, vH[0], vH[1]);
                MMA16816(co[2*dc+1], aPh, vH[2], vH[3]);
                MMA16816(co[2*dc],   aPl, vH[0], vH[1]);
                MMA16816(co[2*dc+1], aPl, vH[2], vH[3]);
            }
        }

        __syncthreads();
        if (j < qt) { KFILL(j + 1); VFILL(j + 1); }
    }
#undef KFILL
#undef VFILL

    // ---- epilogue: write AO hi-only fp16 (stride 2048) ----
    float i0 = 1.f / l0v, i1 = 1.f / l1v;
    const int b = bh >> 4, h = bh & 15;
    int g = lane >> 2, t2 = (lane & 3) * 2;
    const int r0 = b * 2048 + q0 + wid * 16 + g;
    const int cbase = h * 128 + t2;
#pragma unroll
    for (int nt = 0; nt < 16; nt++) {
        const int cc = cbase + nt * 8;
        *(uint32_t*)(AO + (size_t)r0 * 2048 + cc) =
            pack_f16x2(co[nt][0] * i0, co[nt][1] * i0);
        *(uint32_t*)(AO + (size_t)(r0 + 8) * 2048 + cc) =
            pack_f16x2(co[nt][2] * i1, co[nt][3] * i1);
    }
}

// ===========================================================================
extern "C" void kernel_launch(void* const* d_in, const int* in_sizes, int n_in,
                              void* d_out, int out_size)
{
    const float* x  = (const float*)d_in[0];
    const float* WQ = (const float*)d_in[1];
    const float* WK = (const float*)d_in[2];
    const float* WV = (const float*)d_in[3];
    const float* WO = (const float*)d_in[4];
    const int*  pos = (const int*)d_in[5];
    float* out = (float*)d_out;

    __half *Axp, *Aaop, *Wqp, *Wkp, *Wvp, *Wop;
    __half *Qhp, *Qlp, *Khp, *Vhp;
    cudaGetSymbolAddress((void**)&Axp, g_Ax);
    cudaGetSymbolAddress((void**)&Aaop, g_Aao);
    cudaGetSymbolAddress((void**)&Wqp, g_Wq);
    cudaGetSymbolAddress((void**)&Wkp, g_Wk);
    cudaGetSymbolAddress((void**)&Wvp, g_Wv);
    cudaGetSymbolAddress((void**)&Wop, g_Wo);
    cudaGetSymbolAddress((void**)&Qhp, g_Qh);
    cudaGetSymbolAddress((void**)&Qlp, g_Ql);
    cudaGetSymbolAddress((void**)&Khp, g_Kh);
    cudaGetSymbolAddress((void**)&Vhp, g_Vh);

    prep<<<8192 + 4 * 4096, 256>>>(x, WQ, WK, WV, WO, Axp, Wqp, Wkp, Wvp, Wop);

    cudaFuncSetAttribute(gemm_qkv_fused, cudaFuncAttributeMaxDynamicSharedMemorySize, GSMEM);
    cudaFuncSetAttribute(gemm_out,       cudaFuncAttributeMaxDynamicSharedMemorySize, GSMEM);

    gemm_qkv_fused<<<dim3(Dm / 128, Mrows / 128, 3), 256, GSMEM>>>(Axp, Wqp, Wkp, Wvp, pos);

    cudaFuncSetAttribute(flash_f16, cudaFuncAttributeMaxDynamicSharedMemorySize, 4 * 17408);
    flash_f16<<<dim3(Sseq / 64, Bb * Hh), 128, 4 * 17408>>>(Qhp, Qlp, Khp, Vhp, Aaop);

    gemm_out<<<dim3(Dm / 128, Mrows / 128), 256, GSMEM>>>(Aaop, Wop, out);
}

// round 14
// speedup vs baseline: 1.7068x; 1.1345x over previous
#include <cuda_runtime.h>
#include <cuda_fp16.h>
#include <math.h>
#include <cstdint>

#define Dm   2048
#define Bb   2
#define Sseq 2048
#define Hh   16
#define DKk  128
#define Mrows 4096
#define SCALE 0.08838834764831844055f  // 1/sqrt(128)

__device__ float g_invf[64];

// dense fp16 hi operands, stride 2048
__device__ __half g_Ax[(size_t)Mrows * 2048];
__device__ __half g_Aao[(size_t)Mrows * 2048];
__device__ __half g_Wq[(size_t)Dm * 2048];
__device__ __half g_Wk[(size_t)Dm * 2048];
__device__ __half g_Wv[(size_t)Dm * 2048];
__device__ __half g_Wo[(size_t)Dm * 2048];

// per-head fp16 Q/K/V for flash:  [bh][s][128]
#define HS ((size_t)32 * 2048 * 128)
__device__ __half g_Qh[HS];
__device__ __half g_Kh[HS];
__device__ __half g_Vh[HS];

__device__ __forceinline__ uint32_t smem_to_u32(const void* p) {
    uint32_t a;
    asm("{ .reg .u64 t; cvta.to.shared.u64 t, %1; cvt.u32.u64 %0, t; }"
        : "=r"(a) : "l"(p));
    return a;
}
__device__ __forceinline__ void cpa16(uint32_t d, const void* g) {
    asm volatile("cp.async.cg.shared.global [%0], [%1], 16;" :: "r"(d), "l"(g) : "memory");
}
__device__ __forceinline__ uint32_t pack_f16x2(float lo, float hi) {
    uint32_t r;
    asm("cvt.rn.f16x2.f32 %0, %1, %2;" : "=r"(r) : "f"(hi), "f"(lo));
    return r;
}
__device__ __forceinline__ float f16rt(float x) {
    return __half2float(__float2half_rn(x));
}

#define LDSM4(R, addr) \
    asm volatile("ldmatrix.sync.aligned.m8n8.x4.shared.b16 {%0,%1,%2,%3}, [%4];" \
        : "=r"((R)[0]), "=r"((R)[1]), "=r"((R)[2]), "=r"((R)[3]) : "r"(addr))
#define LDSM4T(R, addr) \
    asm volatile("ldmatrix.sync.aligned.m8n8.x4.trans.shared.b16 {%0,%1,%2,%3}, [%4];" \
        : "=r"((R)[0]), "=r"((R)[1]), "=r"((R)[2]), "=r"((R)[3]) : "r"(addr))
#define MMA16816(C, A, B0, B1) \
    asm volatile("mma.sync.aligned.m16n8k16.row.col.f32.f16.f16.f32 " \
        "{%0,%1,%2,%3}, {%4,%5,%6,%7}, {%8,%9}, {%0,%1,%2,%3};" \
        : "+f"((C)[0]), "+f"((C)[1]), "+f"((C)[2]), "+f"((C)[3]) \
        : "r"((A)[0]), "r"((A)[1]), "r"((A)[2]), "r"((A)[3]), "r"(B0), "r"(B1))

// ===========================================================================
// fp32 [R,2048] -> fp16 hi-only [R,2048]. One launch: freqs + x + 4 weights.
// ===========================================================================
__device__ __forceinline__
void conv_hi(const float* __restrict__ X, __half* __restrict__ Y, int idx)
{
    int r  = idx >> 9;
    int c4 = idx & 511;
    float4 v = *(const float4*)(X + ((size_t)r << 11) + (c4 << 2));
    __half2 hA = __halves2half2(__float2half_rn(v.x), __float2half_rn(v.y));
    __half2 hB = __halves2half2(__float2half_rn(v.z), __float2half_rn(v.w));
    __half2* p = (__half2*)(Y + ((size_t)r << 11) + (c4 << 2));
    p[0] = hA; p[1] = hB;
}

__global__ __launch_bounds__(256)
void prep(const float* __restrict__ x,
          const float* __restrict__ W0, const float* __restrict__ W1,
          const float* __restrict__ W2, const float* __restrict__ W3,
          __half* __restrict__ Yx,
          __half* __restrict__ Y0, __half* __restrict__ Y1,
          __half* __restrict__ Y2, __half* __restrict__ Y3)
{
    int bid = blockIdx.x, tid = threadIdx.x;
    if (bid == 0 && tid < 64)
        g_invf[tid] = (float)pow(10000.0, -(double)tid / 64.0);

    if (bid < 8192) {
        conv_hi(x, Yx, bid * 256 + tid);
    } else {
        int w   = (bid - 8192) >> 12;            // 0..3
        int sub = (bid - 8192) & 4095;
        const float* W = (w == 0) ? W0 : (w == 1) ? W1 : (w == 2) ? W2 : W3;
        __half*      Y = (w == 0) ? Y0 : (w == 1) ? Y1 : (w == 2) ? Y2 : Y3;
        conv_hi(W, Y, sub * 256 + tid);
    }
}

// ===========================================================================
// GEMM mainloop: CTA 128x128, BK=64 (pitch 144B), 3-stage cp.async,
// 8 warps (2x4), warp 64x32. K'=2048 (32 slabs), stride 2048.
// ===========================================================================
#define SPITCH 144u
#define STG_OP (128u * SPITCH)          // 18432 B per operand per stage
#define STG_BOTH (2u * STG_OP)          // 36864 per stage
#define GSMEM (3u * STG_BOTH)           // 110592 total
#define KTN 32

__device__ __forceinline__
void gemm_mainloop(const __half* __restrict__ A,
                   const __half* __restrict__ B,
                   float c[4][4][4])
{
    extern __shared__ __align__(128) char gsm[];
    const uint32_t sbase = smem_to_u32(gsm);
    const int tid = threadIdx.x;
    const int lane = tid & 31, wid = tid >> 5;
    const int bm = blockIdx.y * 128, bn = blockIdx.x * 128;
    const int wm = (wid >> 2) * 64, wn = (wid & 3) * 32;

    const __half* Ag = A + ((size_t)bm << 11);
    const __half* Bg = B + ((size_t)bn << 11);

#pragma unroll
    for (int i = 0; i < 4; i++)
#pragma unroll
        for (int j = 0; j < 4; j++)
#pragma unroll
            for (int k = 0; k < 4; k++) c[i][j][k] = 0.f;

    const int frow = tid >> 3;          // 0..31 (+32*j)
    const int fseg = tid & 7;           // 0..7

#define GFILL(s) do {                                                         \
        uint32_t _st = sbase + (uint32_t)((s) % 3) * STG_BOTH;                \
        int _ks = (s) * 64;                                                   \
        _Pragma("unroll")                                                     \
        for (int _j = 0; _j < 4; _j++) {                                      \
            int _row = frow + _j * 32;                                        \
            uint32_t _d = (uint32_t)(_row * SPITCH + fseg * 16);              \
            const void* _ga = Ag + ((size_t)_row << 11) + _ks + fseg * 8;     \
            const void* _gb = Bg + ((size_t)_row << 11) + _ks + fseg * 8;     \
            cpa16(_st + _d, _ga); cpa16(_st + STG_OP + _d, _gb);              \
        }                                                                     \
        asm volatile("cp.async.commit_group;" ::: "memory");                  \
    } while (0)

    GFILL(0); GFILL(1);

    const uint32_t aRowOff = (uint32_t)((wm + (lane & 15)) * SPITCH);
    const uint32_t bRowOff = (uint32_t)((wn + (lane & 7) + ((lane >> 4) << 3)) * SPITCH);
    const uint32_t aColOff = (uint32_t)((lane >> 4) << 4);
    const uint32_t bColOff = (uint32_t)(((lane >> 3) & 1) << 4);

    for (int kt = 0; kt < KTN; kt++) {
        asm volatile("cp.async.wait_group 1;" ::: "memory");
        __syncthreads();
        if (kt + 2 < KTN) { GFILL(kt + 2); }
        else { asm volatile("cp.async.commit_group;" ::: "memory"); }

        const uint32_t st = sbase + (uint32_t)(kt % 3) * STG_BOTH;
        const uint32_t sa = st, sb = st + STG_OP;

#pragma unroll
        for (int ks = 0; ks < 4; ks++) {
            uint32_t a[4][4], bf[2][4];
            const uint32_t ac = ks * 32 + aColOff;
            const uint32_t bc = ks * 32 + bColOff;
#pragma unroll
            for (int mt = 0; mt < 4; mt++)
                LDSM4(a[mt], sa + aRowOff + (uint32_t)(mt * 16) * SPITCH + ac);
#pragma unroll
            for (int nt2 = 0; nt2 < 2; nt2++)
                LDSM4(bf[nt2], sb + bRowOff + (uint32_t)(nt2 * 16) * SPITCH + bc);
#pragma unroll
            for (int mt = 0; mt < 4; mt++)
#pragma unroll
                for (int nt = 0; nt < 4; nt++)
                    MMA16816(c[mt][nt], a[mt],
                             bf[nt >> 1][(nt & 1) * 2], bf[nt >> 1][(nt & 1) * 2 + 1]);
        }
    }
#undef GFILL
}

// ===========================================================================
// QKV GEMM with fused RoPE + scale epilogue; hi-only fp16 outputs.
// z=0: Q (rope+scale), z=1: K (rope), z=2: V.
// ===========================================================================
__global__ __launch_bounds__(256, 2)
void gemm_qkv_fused(const __half* __restrict__ A,
                    const __half* __restrict__ WQ, const __half* __restrict__ WK,
                    const __half* __restrict__ WV,
                    const int* __restrict__ pos)
{
    const int z = blockIdx.z;
    const __half* Bw = (z == 0) ? WQ : (z == 1) ? WK : WV;

    float c[4][4][4];
    gemm_mainloop(A, Bw, c);

    __half* HI = (z == 0) ? g_Qh : (z == 1) ? g_Kh : g_Vh;

    const int lane = threadIdx.x & 31, wid = threadIdx.x >> 5;
    const int bm = blockIdx.y * 128, bn = blockIdx.x * 128;
    const int wm = (wid >> 2) * 64, wn = (wid & 3) * 32;
    const int r0 = bm + wm + (lane >> 2);
    const int c0 = bn + wn + (lane & 3) * 2;

#pragma unroll
    for (int mt = 0; mt < 4; mt++) {
#pragma unroll
        for (int half = 0; half < 2; half++) {
            const int rr = r0 + mt * 16 + half * 8;
            const int b = rr >> 11, s = rr & 2047;
            const int p = pos[s];
#pragma unroll
            for (int nt = 0; nt < 4; nt++) {
                const int cc = c0 + nt * 8;
                const int h = cc >> 7, dk = cc & 127;
                float v0 = c[mt][nt][half * 2], v1 = c[mt][nt][half * 2 + 1];
                if (z < 2) {
                    const int i = dk >> 1;
                    float ang = (float)p * g_invf[i];
                    float sn, cs;
                    sincosf(ang, &sn, &cs);
                    float r1 = v0 * cs - v1 * sn;
                    float r2 = v0 * sn + v1 * cs;
                    v0 = r1; v1 = r2;
                    if (z == 0) { v0 *= SCALE; v1 *= SCALE; }
                }
                size_t dst = (((size_t)(b * 16 + h) << 11) + s) * 128 + dk;
                *(uint32_t*)(HI + dst) = pack_f16x2(v0, v1);
            }
        }
    }
}

// ===========================================================================
// Final GEMM: out = AOhi * Wohi^T, plain fp32 epilogue
// ===========================================================================
__global__ __launch_bounds__(256, 2)
void gemm_out(const __half* __restrict__ A, const __half* __restrict__ B,
              float* __restrict__ C)
{
    float c[4][4][4];
    gemm_mainloop(A, B, c);

    const int lane = threadIdx.x & 31, wid = threadIdx.x >> 5;
    const int bm = blockIdx.y * 128, bn = blockIdx.x * 128;
    const int wm = (wid >> 2) * 64, wn = (wid & 3) * 32;
    const int r0 = bm + wm + (lane >> 2);
    const int c0 = bn + wn + (lane & 3) * 2;
#pragma unroll
    for (int mt = 0; mt < 4; mt++)
#pragma unroll
        for (int nt = 0; nt < 4; nt++) {
            int rr = r0 + mt * 16, cc = c0 + nt * 8;
            *(float2*)(C + (size_t)rr * Dm + cc)       = make_float2(c[mt][nt][0], c[mt][nt][1]);
            *(float2*)(C + (size_t)(rr + 8) * Dm + cc) = make_float2(c[mt][nt][2], c[mt][nt][3]);
        }
}

// ===========================================================================
// Tensor-core flash attention, causal. Scores hi-only fp16 (1 QK pass);
// PV keeps P two-term. BQ=BKV=64, 128 threads, 3 tiles -> 4 CTA/SM.
// K/V separate commit groups (V load overlaps QK+softmax).
// ===========================================================================
#define FPB 272
#define TILEB ((uint32_t)(64 * FPB))   // 17408 bytes
#define FSMEM (3u * TILEB)             // 52224

__global__ __launch_bounds__(128, 4)
void flash_f16(const __half* __restrict__ Qh, const __half* __restrict__ Kh,
               const __half* __restrict__ Vh, __half* __restrict__ AO)
{
    extern __shared__ __align__(128) __half fsm[];
    const uint32_t sb = smem_to_u32(fsm);
    const uint32_t uQh = sb, uKh = sb + TILEB, uVh = sb + 2 * TILEB;

    const int tid = threadIdx.x, lane = tid & 31, wid = tid >> 5;
    const int qt = (int)gridDim.x - 1 - (int)blockIdx.x;
    const int bh = blockIdx.y;
    const int q0 = qt * 64;
    const size_t hbase = (size_t)bh * (2048 * 128);

#pragma unroll
    for (int i = 0; i < 8; i++) {
        int cc = tid + i * 128, row = cc >> 4, seg = cc & 15;
        uint32_t d = (uint32_t)(row * FPB + seg * 16);
        cpa16(uQh + d, Qh + hbase + (size_t)(q0 + row) * 128 + seg * 8);
    }
    asm volatile("cp.async.commit_group;" ::: "memory");

#define KFILL(jj) do {                                                         \
        int _c0 = (jj) * 64;                                                   \
        _Pragma("unroll")                                                      \
        for (int _i = 0; _i < 8; _i++) {                                       \
            int _cc = tid + _i * 128, _row = _cc >> 4, _seg = _cc & 15;        \
            uint32_t _d = (uint32_t)(_row * FPB + _seg * 16);                  \
            cpa16(uKh + _d, Kh + hbase + (size_t)(_c0 + _row) * 128 + _seg * 8); \
        }                                                                      \
        asm volatile("cp.async.commit_group;" ::: "memory");                   \
    } while (0)
#define VFILL(jj) do {                                                         \
        int _c0 = (jj) * 64;                                                   \
        _Pragma("unroll")                                                      \
        for (int _i = 0; _i < 8; _i++) {                                       \
            int _cc = tid + _i * 128, _row = _cc >> 4, _seg = _cc & 15;        \
            uint32_t _d = (uint32_t)(_row * FPB + _seg * 16);                  \
            cpa16(uVh + _d, Vh + hbase + (size_t)(_c0 + _row) * 128 + _seg * 8); \
        }                                                                      \
        asm volatile("cp.async.commit_group;" ::: "memory");                   \
    } while (0)

    KFILL(0); VFILL(0);

    float co[16][4];
#pragma unroll
    for (int i = 0; i < 16; i++)
#pragma unroll
        for (int k = 0; k < 4; k++) co[i][k] = 0.f;
    float m0v = -1e30f, m1v = -1e30f, l0v = 0.f, l1v = 0.f;

    const uint32_t aoff  = (uint32_t)((wid * 16 + (lane & 15)) * FPB + ((lane >> 4) << 4));
    const uint32_t bKoff = (uint32_t)(((lane & 7) + ((lane >> 4) << 3)) * FPB + (((lane >> 3) & 1) << 4));
    const uint32_t vloff = (uint32_t)((lane & 15) * FPB + ((lane >> 4) << 4));

    for (int j = 0; j <= qt; j++) {
        asm volatile("cp.async.wait_group 1;" ::: "memory");
        __syncthreads();

        float cs[8][4];
#pragma unroll
        for (int i = 0; i < 8; i++)
#pragma unroll
            for (int k = 0; k < 4; k++) cs[i][k] = 0.f;

#pragma unroll
        for (int ks = 0; ks < 8; ks++) {
            uint32_t aH[4];
            LDSM4(aH, uQh + aoff + ks * 32);
#pragma unroll
            for (int np = 0; np < 4; np++) {
                uint32_t bH[4];
                uint32_t bo = bKoff + (uint32_t)(np * 16 * FPB) + ks * 32;
                LDSM4(bH, uKh + bo);
                MMA16816(cs[2*np],   aH, bH[0], bH[1]);
                MMA16816(cs[2*np+1], aH, bH[2], bH[3]);
            }
        }

        if (j == qt) {
            int g = lane >> 2, t2 = (lane & 3) * 2;
            int r0 = wid * 16 + g, r1 = r0 + 8;
#pragma unroll
            for (int nt = 0; nt < 8; nt++) {
                int cl = nt * 8 + t2;
                if (cl     > r0) cs[nt][0] = -1e30f;
                if (cl + 1 > r0) cs[nt][1] = -1e30f;
                if (cl     > r1) cs[nt][2] = -1e30f;
                if (cl + 1 > r1) cs[nt][3] = -1e30f;
            }
        }

        float mx0 = -1e30f, mx1 = -1e30f;
#pragma unroll
        for (int nt = 0; nt < 8; nt++) {
            mx0 = fmaxf(mx0, fmaxf(cs[nt][0], cs[nt][1]));
            mx1 = fmaxf(mx1, fmaxf(cs[nt][2], cs[nt][3]));
        }
        mx0 = fmaxf(mx0, __shfl_xor_sync(0xffffffffu, mx0, 1));
        mx0 = fmaxf(mx0, __shfl_xor_sync(0xffffffffu, mx0, 2));
        mx1 = fmaxf(mx1, __shfl_xor_sync(0xffffffffu, mx1, 1));
        mx1 = fmaxf(mx1, __shfl_xor_sync(0xffffffffu, mx1, 2));
        float mn0 = fmaxf(m0v, mx0), mn1 = fmaxf(m1v, mx1);
        float al0 = __expf(m0v - mn0), al1 = __expf(m1v - mn1);
        m0v = mn0; m1v = mn1;
        float rs0 = 0.f, rs1 = 0.f;
#pragma unroll
        for (int nt = 0; nt < 8; nt++) {
            cs[nt][0] = __expf(cs[nt][0] - mn0);
            cs[nt][1] = __expf(cs[nt][1] - mn0);
            cs[nt][2] = __expf(cs[nt][2] - mn1);
            cs[nt][3] = __expf(cs[nt][3] - mn1);
            rs0 += cs[nt][0] + cs[nt][1];
            rs1 += cs[nt][2] + cs[nt][3];
        }
        rs0 += __shfl_xor_sync(0xffffffffu, rs0, 1);
        rs0 += __shfl_xor_sync(0xffffffffu, rs0, 2);
        rs1 += __shfl_xor_sync(0xffffffffu, rs1, 1);
        rs1 += __shfl_xor_sync(0xffffffffu, rs1, 2);
        l0v = l0v * al0 + rs0;
        l1v = l1v * al1 + rs1;
#pragma unroll
        for (int nt = 0; nt < 16; nt++) {
            co[nt][0] *= al0; co[nt][1] *= al0;
            co[nt][2] *= al1; co[nt][3] *= al1;
        }

        asm volatile("cp.async.wait_group 0;" ::: "memory");
        __syncthreads();

#pragma unroll
        for (int ks = 0; ks < 4; ks++) {
            float p0 = cs[2*ks][0],   p1 = cs[2*ks][1],   p2 = cs[2*ks][2],   p3 = cs[2*ks][3];
            float p4 = cs[2*ks+1][0], p5 = cs[2*ks+1][1], p6 = cs[2*ks+1][2], p7 = cs[2*ks+1][3];
            uint32_t aPh[4] = { pack_f16x2(p0, p1), pack_f16x2(p2, p3),
                                pack_f16x2(p4, p5), pack_f16x2(p6, p7) };
            uint32_t aPl[4] = {
                pack_f16x2(p0 - f16rt(p0), p1 - f16rt(p1)),
                pack_f16x2(p2 - f16rt(p2), p3 - f16rt(p3)),
                pack_f16x2(p4 - f16rt(p4), p5 - f16rt(p5)),
                pack_f16x2(p6 - f16rt(p6), p7 - f16rt(p7)) };
            uint32_t vb = vloff + (uint32_t)(ks * 16 * FPB);
#pragma unroll
            for (int dc = 0; dc < 8; dc++) {
                uint32_t vH[4];
                LDSM4T(vH, uVh + vb + dc * 32);
                MMA16816(co[2*dc],   aPh, vH[0], vH[1]);
                MMA16816(co[2*dc+1], aPh, vH[2], vH[3]);
                MMA16816(co[2*dc],   aPl, vH[0], vH[1]);
                MMA16816(co[2*dc+1], aPl, vH[2], vH[3]);
            }
        }

        __syncthreads();
        if (j < qt) { KFILL(j + 1); VFILL(j + 1); }
    }
#undef KFILL
#undef VFILL

    // ---- epilogue: write AO hi-only fp16 (stride 2048) ----
    float i0 = 1.f / l0v, i1 = 1.f / l1v;
    const int b = bh >> 4, h = bh & 15;
    int g = lane >> 2, t2 = (lane & 3) * 2;
    const int r0 = b * 2048 + q0 + wid * 16 + g;
    const int cbase = h * 128 + t2;
#pragma unroll
    for (int nt = 0; nt < 16; nt++) {
        const int cc = cbase + nt * 8;
        *(uint32_t*)(AO + ((size_t)r0 << 11) + cc) =
            pack_f16x2(co[nt][0] * i0, co[nt][1] * i0);
        *(uint32_t*)(AO + ((size_t)(r0 + 8) << 11) + cc) =
            pack_f16x2(co[nt][2] * i1, co[nt][3] * i1);
    }
}

// ===========================================================================
extern "C" void kernel_launch(void* const* d_in, const int* in_sizes, int n_in,
                              void* d_out, int out_size)
{
    const float* x  = (const float*)d_in[0];
    const float* WQ = (const float*)d_in[1];
    const float* WK = (const float*)d_in[2];
    const float* WV = (const float*)d_in[3];
    const float* WO = (const float*)d_in[4];
    const int*  pos = (const int*)d_in[5];
    float* out = (float*)d_out;

    __half *Axp, *Aaop, *Wqp, *Wkp, *Wvp, *Wop;
    __half *Qhp, *Khp, *Vhp;
    cudaGetSymbolAddress((void**)&Axp, g_Ax);
    cudaGetSymbolAddress((void**)&Aaop, g_Aao);
    cudaGetSymbolAddress((void**)&Wqp, g_Wq);
    cudaGetSymbolAddress((void**)&Wkp, g_Wk);
    cudaGetSymbolAddress((void**)&Wvp, g_Wv);
    cudaGetSymbolAddress((void**)&Wop, g_Wo);
    cudaGetSymbolAddress((void**)&Qhp, g_Qh);
    cudaGetSymbolAddress((void**)&Khp, g_Kh);
    cudaGetSymbolAddress((void**)&Vhp, g_Vh);

    prep<<<8192 + 4 * 4096, 256>>>(x, WQ, WK, WV, WO, Axp, Wqp, Wkp, Wvp, Wop);

    cudaFuncSetAttribute(gemm_qkv_fused, cudaFuncAttributeMaxDynamicSharedMemorySize, GSMEM);
    cudaFuncSetAttribute(gemm_out,       cudaFuncAttributeMaxDynamicSharedMemorySize, GSMEM);

    gemm_qkv_fused<<<dim3(Dm / 128, Mrows / 128, 3), 256, GSMEM>>>(Axp, Wqp, Wkp, Wvp, pos);

    cudaFuncSetAttribute(flash_f16, cudaFuncAttributeMaxDynamicSharedMemorySize, FSMEM);
    flash_f16<<<dim3(Sseq / 64, Bb * Hh), 128, FSMEM>>>(Qhp, Khp, Vhp, Aaop);

    gemm_out<<<dim3(Dm / 128, Mrows / 128), 256, GSMEM>>>(Aaop, Wop, out);
}

// round 15
// speedup vs baseline: 1.8345x; 1.0749x over previous
#include <cuda_runtime.h>
#include <cuda_fp16.h>
#include <math.h>
#include <cstdint>

#define Dm   2048
#define Bb   2
#define Sseq 2048
#define Hh   16
#define DKk  128
#define Mrows 4096
#define SCALE 0.08838834764831844055f  // 1/sqrt(128)

__device__ float g_invf[64];

// dense fp16 hi operands, stride 2048
__device__ __half g_Ax[(size_t)Mrows * 2048];
__device__ __half g_Aao[(size_t)Mrows * 2048];
__device__ __half g_Wq[(size_t)Dm * 2048];
__device__ __half g_Wk[(size_t)Dm * 2048];
__device__ __half g_Wv[(size_t)Dm * 2048];
__device__ __half g_Wo[(size_t)Dm * 2048];

// per-head fp16 Q/K/V for flash:  [bh][s][128]
#define HS ((size_t)32 * 2048 * 128)
__device__ __half g_Qh[HS];
__device__ __half g_Kh[HS];
__device__ __half g_Vh[HS];

__device__ __forceinline__ uint32_t smem_to_u32(const void* p) {
    uint32_t a;
    asm("{ .reg .u64 t; cvta.to.shared.u64 t, %1; cvt.u32.u64 %0, t; }"
        : "=r"(a) : "l"(p));
    return a;
}
__device__ __forceinline__ void cpa16(uint32_t d, const void* g) {
    asm volatile("cp.async.cg.shared.global [%0], [%1], 16;" :: "r"(d), "l"(g) : "memory");
}
__device__ __forceinline__ uint32_t pack_f16x2(float lo, float hi) {
    uint32_t r;
    asm("cvt.rn.f16x2.f32 %0, %1, %2;" : "=r"(r) : "f"(hi), "f"(lo));
    return r;
}

#define LDSM4(R, addr) \
    asm volatile("ldmatrix.sync.aligned.m8n8.x4.shared.b16 {%0,%1,%2,%3}, [%4];" \
        : "=r"((R)[0]), "=r"((R)[1]), "=r"((R)[2]), "=r"((R)[3]) : "r"(addr))
#define LDSM4T(R, addr) \
    asm volatile("ldmatrix.sync.aligned.m8n8.x4.trans.shared.b16 {%0,%1,%2,%3}, [%4];" \
        : "=r"((R)[0]), "=r"((R)[1]), "=r"((R)[2]), "=r"((R)[3]) : "r"(addr))
#define MMA16816(C, A, B0, B1) \
    asm volatile("mma.sync.aligned.m16n8k16.row.col.f32.f16.f16.f32 " \
        "{%0,%1,%2,%3}, {%4,%5,%6,%7}, {%8,%9}, {%0,%1,%2,%3};" \
        : "+f"((C)[0]), "+f"((C)[1]), "+f"((C)[2]), "+f"((C)[3]) \
        : "r"((A)[0]), "r"((A)[1]), "r"((A)[2]), "r"((A)[3]), "r"(B0), "r"(B1))

// ===========================================================================
// fp32 [R,2048] -> fp16 hi-only [R,2048]. One launch: freqs + x + 4 weights.
// ===========================================================================
__device__ __forceinline__
void conv_hi(const float* __restrict__ X, __half* __restrict__ Y, int idx)
{
    int r  = idx >> 9;
    int c4 = idx & 511;
    float4 v = *(const float4*)(X + ((size_t)r << 11) + (c4 << 2));
    __half2 hA = __halves2half2(__float2half_rn(v.x), __float2half_rn(v.y));
    __half2 hB = __halves2half2(__float2half_rn(v.z), __float2half_rn(v.w));
    __half2* p = (__half2*)(Y + ((size_t)r << 11) + (c4 << 2));
    p[0] = hA; p[1] = hB;
}

__global__ __launch_bounds__(256)
void prep(const float* __restrict__ x,
          const float* __restrict__ W0, const float* __restrict__ W1,
          const float* __restrict__ W2, const float* __restrict__ W3,
          __half* __restrict__ Yx,
          __half* __restrict__ Y0, __half* __restrict__ Y1,
          __half* __restrict__ Y2, __half* __restrict__ Y3)
{
    int bid = blockIdx.x, tid = threadIdx.x;
    if (bid == 0 && tid < 64)
        g_invf[tid] = (float)pow(10000.0, -(double)tid / 64.0);

    if (bid < 8192) {
        conv_hi(x, Yx, bid * 256 + tid);
    } else {
        int w   = (bid - 8192) >> 12;            // 0..3
        int sub = (bid - 8192) & 4095;
        const float* W = (w == 0) ? W0 : (w == 1) ? W1 : (w == 2) ? W2 : W3;
        __half*      Y = (w == 0) ? Y0 : (w == 1) ? Y1 : (w == 2) ? Y2 : Y3;
        conv_hi(W, Y, sub * 256 + tid);
    }
}

// ===========================================================================
// GEMM mainloop: CTA 128x128, BK=64 (pitch 144B), 3-stage cp.async,
// 8 warps (2x4), warp 64x32. K'=2048 (32 slabs), stride 2048.
// ===========================================================================
#define SPITCH 144u
#define STG_OP (128u * SPITCH)          // 18432 B per operand per stage
#define STG_BOTH (2u * STG_OP)          // 36864 per stage
#define GSMEM (3u * STG_BOTH)           // 110592 total
#define KTN 32

__device__ __forceinline__
void gemm_mainloop(const __half* __restrict__ A,
                   const __half* __restrict__ B,
                   float c[4][4][4])
{
    extern __shared__ __align__(128) char gsm[];
    const uint32_t sbase = smem_to_u32(gsm);
    const int tid = threadIdx.x;
    const int lane = tid & 31, wid = tid >> 5;
    const int bm = blockIdx.y * 128, bn = blockIdx.x * 128;
    const int wm = (wid >> 2) * 64, wn = (wid & 3) * 32;

    const __half* Ag = A + ((size_t)bm << 11);
    const __half* Bg = B + ((size_t)bn << 11);

#pragma unroll
    for (int i = 0; i < 4; i++)
#pragma unroll
        for (int j = 0; j < 4; j++)
#pragma unroll
            for (int k = 0; k < 4; k++) c[i][j][k] = 0.f;

    const int frow = tid >> 3;          // 0..31 (+32*j)
    const int fseg = tid & 7;           // 0..7

#define GFILL(s) do {                                                         \
        uint32_t _st = sbase + (uint32_t)((s) % 3) * STG_BOTH;                \
        int _ks = (s) * 64;                                                   \
        _Pragma("unroll")                                                     \
        for (int _j = 0; _j < 4; _j++) {                                      \
            int _row = frow + _j * 32;                                        \
            uint32_t _d = (uint32_t)(_row * SPITCH + fseg * 16);              \
            const void* _ga = Ag + ((size_t)_row << 11) + _ks + fseg * 8;     \
            const void* _gb = Bg + ((size_t)_row << 11) + _ks + fseg * 8;     \
            cpa16(_st + _d, _ga); cpa16(_st + STG_OP + _d, _gb);              \
        }                                                                     \
        asm volatile("cp.async.commit_group;" ::: "memory");                  \
    } while (0)

    GFILL(0); GFILL(1);

    const uint32_t aRowOff = (uint32_t)((wm + (lane & 15)) * SPITCH);
    const uint32_t bRowOff = (uint32_t)((wn + (lane & 7) + ((lane >> 4) << 3)) * SPITCH);
    const uint32_t aColOff = (uint32_t)((lane >> 4) << 4);
    const uint32_t bColOff = (uint32_t)(((lane >> 3) & 1) << 4);

    for (int kt = 0; kt < KTN; kt++) {
        asm volatile("cp.async.wait_group 1;" ::: "memory");
        __syncthreads();
        if (kt + 2 < KTN) { GFILL(kt + 2); }
        else { asm volatile("cp.async.commit_group;" ::: "memory"); }

        const uint32_t st = sbase + (uint32_t)(kt % 3) * STG_BOTH;
        const uint32_t sa = st, sb = st + STG_OP;

#pragma unroll
        for (int ks = 0; ks < 4; ks++) {
            uint32_t a[4][4], bf[2][4];
            const uint32_t ac = ks * 32 + aColOff;
            const uint32_t bc = ks * 32 + bColOff;
#pragma unroll
            for (int mt = 0; mt < 4; mt++)
                LDSM4(a[mt], sa + aRowOff + (uint32_t)(mt * 16) * SPITCH + ac);
#pragma unroll
            for (int nt2 = 0; nt2 < 2; nt2++)
                LDSM4(bf[nt2], sb + bRowOff + (uint32_t)(nt2 * 16) * SPITCH + bc);
#pragma unroll
            for (int mt = 0; mt < 4; mt++)
#pragma unroll
                for (int nt = 0; nt < 4; nt++)
                    MMA16816(c[mt][nt], a[mt],
                             bf[nt >> 1][(nt & 1) * 2], bf[nt >> 1][(nt & 1) * 2 + 1]);
        }
    }
#undef GFILL
}

// ===========================================================================
// QKV GEMM with fused RoPE + scale epilogue; hi-only fp16 outputs.
// z=0: Q (rope+scale), z=1: K (rope), z=2: V.
// ===========================================================================
__global__ __launch_bounds__(256, 2)
void gemm_qkv_fused(const __half* __restrict__ A,
                    const __half* __restrict__ WQ, const __half* __restrict__ WK,
                    const __half* __restrict__ WV,
                    const int* __restrict__ pos)
{
    const int z = blockIdx.z;
    const __half* Bw = (z == 0) ? WQ : (z == 1) ? WK : WV;

    float c[4][4][4];
    gemm_mainloop(A, Bw, c);

    __half* HI = (z == 0) ? g_Qh : (z == 1) ? g_Kh : g_Vh;

    const int lane = threadIdx.x & 31, wid = threadIdx.x >> 5;
    const int bm = blockIdx.y * 128, bn = blockIdx.x * 128;
    const int wm = (wid >> 2) * 64, wn = (wid & 3) * 32;
    const int r0 = bm + wm + (lane >> 2);
    const int c0 = bn + wn + (lane & 3) * 2;

#pragma unroll
    for (int mt = 0; mt < 4; mt++) {
#pragma unroll
        for (int half = 0; half < 2; half++) {
            const int rr = r0 + mt * 16 + half * 8;
            const int b = rr >> 11, s = rr & 2047;
            const int p = pos[s];
#pragma unroll
            for (int nt = 0; nt < 4; nt++) {
                const int cc = c0 + nt * 8;
                const int h = cc >> 7, dk = cc & 127;
                float v0 = c[mt][nt][half * 2], v1 = c[mt][nt][half * 2 + 1];
                if (z < 2) {
                    const int i = dk >> 1;
                    float ang = (float)p * g_invf[i];
                    float sn, cs;
                    sincosf(ang, &sn, &cs);
                    float r1 = v0 * cs - v1 * sn;
                    float r2 = v0 * sn + v1 * cs;
                    v0 = r1; v1 = r2;
                    if (z == 0) { v0 *= SCALE; v1 *= SCALE; }
                }
                size_t dst = (((size_t)(b * 16 + h) << 11) + s) * 128 + dk;
                *(uint32_t*)(HI + dst) = pack_f16x2(v0, v1);
            }
        }
    }
}

// ===========================================================================
// Final GEMM: out = AOhi * Wohi^T, plain fp32 epilogue
// ===========================================================================
__global__ __launch_bounds__(256, 2)
void gemm_out(const __half* __restrict__ A, const __half* __restrict__ B,
              float* __restrict__ C)
{
    float c[4][4][4];
    gemm_mainloop(A, B, c);

    const int lane = threadIdx.x & 31, wid = threadIdx.x >> 5;
    const int bm = blockIdx.y * 128, bn = blockIdx.x * 128;
    const int wm = (wid >> 2) * 64, wn = (wid & 3) * 32;
    const int r0 = bm + wm + (lane >> 2);
    const int c0 = bn + wn + (lane & 3) * 2;
#pragma unroll
    for (int mt = 0; mt < 4; mt++)
#pragma unroll
        for (int nt = 0; nt < 4; nt++) {
            int rr = r0 + mt * 16, cc = c0 + nt * 8;
            *(float2*)(C + (size_t)rr * Dm + cc)       = make_float2(c[mt][nt][0], c[mt][nt][1]);
            *(float2*)(C + (size_t)(rr + 8) * Dm + cc) = make_float2(c[mt][nt][2], c[mt][nt][3]);
        }
}

// ===========================================================================
// Tensor-core flash attention, causal. Hi-only fp16 throughout:
// 1 QK pass + 1 PV pass. BQ=BKV=64, 128 threads, 3 tiles -> 4 CTA/SM.
// K/V separate commit groups (V load overlaps QK+softmax).
// ===========================================================================
#define FPB 272
#define TILEB ((uint32_t)(64 * FPB))   // 17408 bytes
#define FSMEM (3u * TILEB)             // 52224

__global__ __launch_bounds__(128, 4)
void flash_f16(const __half* __restrict__ Qh, const __half* __restrict__ Kh,
               const __half* __restrict__ Vh, __half* __restrict__ AO)
{
    extern __shared__ __align__(128) __half fsm[];
    const uint32_t sb = smem_to_u32(fsm);
    const uint32_t uQh = sb, uKh = sb + TILEB, uVh = sb + 2 * TILEB;

    const int tid = threadIdx.x, lane = tid & 31, wid = tid >> 5;
    const int qt = (int)gridDim.x - 1 - (int)blockIdx.x;
    const int bh = blockIdx.y;
    const int q0 = qt * 64;
    const size_t hbase = (size_t)bh * (2048 * 128);

#pragma unroll
    for (int i = 0; i < 8; i++) {
        int cc = tid + i * 128, row = cc >> 4, seg = cc & 15;
        uint32_t d = (uint32_t)(row * FPB + seg * 16);
        cpa16(uQh + d, Qh + hbase + (size_t)(q0 + row) * 128 + seg * 8);
    }
    asm volatile("cp.async.commit_group;" ::: "memory");

#define KFILL(jj) do {                                                         \
        int _c0 = (jj) * 64;                                                   \
        _Pragma("unroll")                                                      \
        for (int _i = 0; _i < 8; _i++) {                                       \
            int _cc = tid + _i * 128, _row = _cc >> 4, _seg = _cc & 15;        \
            uint32_t _d = (uint32_t)(_row * FPB + _seg * 16);                  \
            cpa16(uKh + _d, Kh + hbase + (size_t)(_c0 + _row) * 128 + _seg * 8); \
        }                                                                      \
        asm volatile("cp.async.commit_group;" ::: "memory");                   \
    } while (0)
#define VFILL(jj) do {                                                         \
        int _c0 = (jj) * 64;                                                   \
        _Pragma("unroll")                                                      \
        for (int _i = 0; _i < 8; _i++) {                                       \
            int _cc = tid + _i * 128, _row = _cc >> 4, _seg = _cc & 15;        \
            uint32_t _d = (uint32_t)(_row * FPB + _seg * 16);                  \
            cpa16(uVh + _d, Vh + hbase + (size_t)(_c0 + _row) * 128 + _seg * 8); \
        }                                                                      \
        asm volatile("cp.async.commit_group;" ::: "memory");                   \
    } while (0)

    KFILL(0); VFILL(0);

    float co[16][4];
#pragma unroll
    for (int i = 0; i < 16; i++)
#pragma unroll
        for (int k = 0; k < 4; k++) co[i][k] = 0.f;
    float m0v = -1e30f, m1v = -1e30f, l0v = 0.f, l1v = 0.f;

    const uint32_t aoff  = (uint32_t)((wid * 16 + (lane & 15)) * FPB + ((lane >> 4) << 4));
    const uint32_t bKoff = (uint32_t)(((lane & 7) + ((lane >> 4) << 3)) * FPB + (((lane >> 3) & 1) << 4));
    const uint32_t vloff = (uint32_t)((lane & 15) * FPB + ((lane >> 4) << 4));

    for (int j = 0; j <= qt; j++) {
        asm volatile("cp.async.wait_group 1;" ::: "memory");
        __syncthreads();

        float cs[8][4];
#pragma unroll
        for (int i = 0; i < 8; i++)
#pragma unroll
            for (int k = 0; k < 4; k++) cs[i][k] = 0.f;

#pragma unroll
        for (int ks = 0; ks < 8; ks++) {
            uint32_t aH[4];
            LDSM4(aH, uQh + aoff + ks * 32);
#pragma unroll
            for (int np = 0; np < 4; np++) {
                uint32_t bH[4];
                uint32_t bo = bKoff + (uint32_t)(np * 16 * FPB) + ks * 32;
                LDSM4(bH, uKh + bo);
                MMA16816(cs[2*np],   aH, bH[0], bH[1]);
                MMA16816(cs[2*np+1], aH, bH[2], bH[3]);
            }
        }

        if (j == qt) {
            int g = lane >> 2, t2 = (lane & 3) * 2;
            int r0 = wid * 16 + g, r1 = r0 + 8;
#pragma unroll
            for (int nt = 0; nt < 8; nt++) {
                int cl = nt * 8 + t2;
                if (cl     > r0) cs[nt][0] = -1e30f;
                if (cl + 1 > r0) cs[nt][1] = -1e30f;
                if (cl     > r1) cs[nt][2] = -1e30f;
                if (cl + 1 > r1) cs[nt][3] = -1e30f;
            }
        }

        float mx0 = -1e30f, mx1 = -1e30f;
#pragma unroll
        for (int nt = 0; nt < 8; nt++) {
            mx0 = fmaxf(mx0, fmaxf(cs[nt][0], cs[nt][1]));
            mx1 = fmaxf(mx1, fmaxf(cs[nt][2], cs[nt][3]));
        }
        mx0 = fmaxf(mx0, __shfl_xor_sync(0xffffffffu, mx0, 1));
        mx0 = fmaxf(mx0, __shfl_xor_sync(0xffffffffu, mx0, 2));
        mx1 = fmaxf(mx1, __shfl_xor_sync(0xffffffffu, mx1, 1));
        mx1 = fmaxf(mx1, __shfl_xor_sync(0xffffffffu, mx1, 2));
        float mn0 = fmaxf(m0v, mx0), mn1 = fmaxf(m1v, mx1);
        float al0 = __expf(m0v - mn0), al1 = __expf(m1v - mn1);
        m0v = mn0; m1v = mn1;
        float rs0 = 0.f, rs1 = 0.f;
#pragma unroll
        for (int nt = 0; nt < 8; nt++) {
            cs[nt][0] = __expf(cs[nt][0] - mn0);
            cs[nt][1] = __expf(cs[nt][1] - mn0);
            cs[nt][2] = __expf(cs[nt][2] - mn1);
            cs[nt][3] = __expf(cs[nt][3] - mn1);
            rs0 += cs[nt][0] + cs[nt][1];
            rs1 += cs[nt][2] + cs[nt][3];
        }
        rs0 += __shfl_xor_sync(0xffffffffu, rs0, 1);
        rs0 += __shfl_xor_sync(0xffffffffu, rs0, 2);
        rs1 += __shfl_xor_sync(0xffffffffu, rs1, 1);
        rs1 += __shfl_xor_sync(0xffffffffu, rs1, 2);
        l0v = l0v * al0 + rs0;
        l1v = l1v * al1 + rs1;
#pragma unroll
        for (int nt = 0; nt < 16; nt++) {
            co[nt][0] *= al0; co[nt][1] *= al0;
            co[nt][2] *= al1; co[nt][3] *= al1;
        }

        asm volatile("cp.async.wait_group 0;" ::: "memory");
        __syncthreads();

#pragma unroll
        for (int ks = 0; ks < 4; ks++) {
            uint32_t aPh[4] = { pack_f16x2(cs[2*ks][0],   cs[2*ks][1]),
                                pack_f16x2(cs[2*ks][2],   cs[2*ks][3]),
                                pack_f16x2(cs[2*ks+1][0], cs[2*ks+1][1]),
                                pack_f16x2(cs[2*ks+1][2], cs[2*ks+1][3]) };
            uint32_t vb = vloff + (uint32_t)(ks * 16 * FPB);
#pragma unroll
            for (int dc = 0; dc < 8; dc++) {
                uint32_t vH[4];
                LDSM4T(vH, uVh + vb + dc * 32);
                MMA16816(co[2*dc],   aPh, vH[0], vH[1]);
                MMA16816(co[2*dc+1], aPh, vH[2], vH[3]);
            }
        }

        __syncthreads();
        if (j < qt) { KFILL(j + 1); VFILL(j + 1); }
    }
#undef KFILL
#undef VFILL

    // ---- epilogue: write AO hi-only fp16 (stride 2048) ----
    float i0 = 1.f / l0v, i1 = 1.f / l1v;
    const int b = bh >> 4, h = bh & 15;
    int g = lane >> 2, t2 = (lane & 3) * 2;
    const int r0 = b * 2048 + q0 + wid * 16 + g;
    const int cbase = h * 128 + t2;
#pragma unroll
    for (int nt = 0; nt < 16; nt++) {
        const int cc = cbase + nt * 8;
        *(uint32_t*)(AO + ((size_t)r0 << 11) + cc) =
            pack_f16x2(co[nt][0] * i0, co[nt][1] * i0);
        *(uint32_t*)(AO + ((size_t)(r0 + 8) << 11) + cc) =
            pack_f16x2(co[nt][2] * i1, co[nt][3] * i1);
    }
}

// ===========================================================================
extern "C" void kernel_launch(void* const* d_in, const int* in_sizes, int n_in,
                              void* d_out, int out_size)
{
    const float* x  = (const float*)d_in[0];
    const float* WQ = (const float*)d_in[1];
    const float* WK = (const float*)d_in[2];
    const float* WV = (const float*)d_in[3];
    const float* WO = (const float*)d_in[4];
    const int*  pos = (const int*)d_in[5];
    float* out = (float*)d_out;

    __half *Axp, *Aaop, *Wqp, *Wkp, *Wvp, *Wop;
    __half *Qhp, *Khp, *Vhp;
    cudaGetSymbolAddress((void**)&Axp, g_Ax);
    cudaGetSymbolAddress((void**)&Aaop, g_Aao);
    cudaGetSymbolAddress((void**)&Wqp, g_Wq);
    cudaGetSymbolAddress((void**)&Wkp, g_Wk);
    cudaGetSymbolAddress((void**)&Wvp, g_Wv);
    cudaGetSymbolAddress((void**)&Wop, g_Wo);
    cudaGetSymbolAddress((void**)&Qhp, g_Qh);
    cudaGetSymbolAddress((void**)&Khp, g_Kh);
    cudaGetSymbolAddress((void**)&Vhp, g_Vh);

    prep<<<8192 + 4 * 4096, 256>>>(x, WQ, WK, WV, WO, Axp, Wqp, Wkp, Wvp, Wop);

    cudaFuncSetAttribute(gemm_qkv_fused, cudaFuncAttributeMaxDynamicSharedMemorySize, GSMEM);
    cudaFuncSetAttribute(gemm_out,       cudaFuncAttributeMaxDynamicSharedMemorySize, GSMEM);

    gemm_qkv_fused<<<dim3(Dm / 128, Mrows / 128, 3), 256, GSMEM>>>(Axp, Wqp, Wkp, Wvp, pos);

    cudaFuncSetAttribute(flash_f16, cudaFuncAttributeMaxDynamicSharedMemorySize, FSMEM);
    flash_f16<<<dim3(Sseq / 64, Bb * Hh), 128, FSMEM>>>(Qhp, Khp, Vhp, Aaop);

    gemm_out<<<dim3(Dm / 128, Mrows / 128), 256, GSMEM>>>(Aaop, Wop, out);
}

// round 16
// speedup vs baseline: 1.8625x; 1.0153x over previous
#include <cuda_runtime.h>
#include <cuda_fp16.h>
#include <math.h>
#include <cstdint>

#define Dm   2048
#define Bb   2
#define Sseq 2048
#define Hh   16
#define DKk  128
#define Mrows 4096
#define SCALE 0.08838834764831844055f  // 1/sqrt(128)

__device__ float g_invf[64];

// dense fp16 hi operands, stride 2048
__device__ __half g_Ax[(size_t)Mrows * 2048];
__device__ __half g_Aao[(size_t)Mrows * 2048];
__device__ __half g_Wq[(size_t)Dm * 2048];
__device__ __half g_Wk[(size_t)Dm * 2048];
__device__ __half g_Wv[(size_t)Dm * 2048];
__device__ __half g_Wo[(size_t)Dm * 2048];

// per-head fp16 Q/K/V for flash:  [bh][s][128]
#define HS ((size_t)32 * 2048 * 128)
__device__ __half g_Qh[HS];
__device__ __half g_Kh[HS];
__device__ __half g_Vh[HS];

__device__ __forceinline__ uint32_t smem_to_u32(const void* p) {
    uint32_t a;
    asm("{ .reg .u64 t; cvta.to.shared.u64 t, %1; cvt.u32.u64 %0, t; }"
        : "=r"(a) : "l"(p));
    return a;
}
__device__ __forceinline__ void cpa16(uint32_t d, const void* g) {
    asm volatile("cp.async.cg.shared.global [%0], [%1], 16;" :: "r"(d), "l"(g) : "memory");
}
__device__ __forceinline__ uint32_t pack_f16x2(float lo, float hi) {
    uint32_t r;
    asm("cvt.rn.f16x2.f32 %0, %1, %2;" : "=r"(r) : "f"(hi), "f"(lo));
    return r;
}

#define LDSM4(R, addr) \
    asm volatile("ldmatrix.sync.aligned.m8n8.x4.shared.b16 {%0,%1,%2,%3}, [%4];" \
        : "=r"((R)[0]), "=r"((R)[1]), "=r"((R)[2]), "=r"((R)[3]) : "r"(addr))
#define LDSM4T(R, addr) \
    asm volatile("ldmatrix.sync.aligned.m8n8.x4.trans.shared.b16 {%0,%1,%2,%3}, [%4];" \
        : "=r"((R)[0]), "=r"((R)[1]), "=r"((R)[2]), "=r"((R)[3]) : "r"(addr))
#define MMA16816(C, A, B0, B1) \
    asm volatile("mma.sync.aligned.m16n8k16.row.col.f32.f16.f16.f32 " \
        "{%0,%1,%2,%3}, {%4,%5,%6,%7}, {%8,%9}, {%0,%1,%2,%3};" \
        : "+f"((C)[0]), "+f"((C)[1]), "+f"((C)[2]), "+f"((C)[3]) \
        : "r"((A)[0]), "r"((A)[1]), "r"((A)[2]), "r"((A)[3]), "r"(B0), "r"(B1))

// ===========================================================================
// fp32 [R,2048] -> fp16 hi-only [R,2048]. One launch: freqs + x + 4 weights.
// ===========================================================================
__device__ __forceinline__
void conv_hi(const float* __restrict__ X, __half* __restrict__ Y, int idx)
{
    int r  = idx >> 9;
    int c4 = idx & 511;
    float4 v = *(const float4*)(X + ((size_t)r << 11) + (c4 << 2));
    __half2 hA = __halves2half2(__float2half_rn(v.x), __float2half_rn(v.y));
    __half2 hB = __halves2half2(__float2half_rn(v.z), __float2half_rn(v.w));
    __half2* p = (__half2*)(Y + ((size_t)r << 11) + (c4 << 2));
    p[0] = hA; p[1] = hB;
}

__global__ __launch_bounds__(256)
void prep(const float* __restrict__ x,
          const float* __restrict__ W0, const float* __restrict__ W1,
          const float* __restrict__ W2, const float* __restrict__ W3,
          __half* __restrict__ Yx,
          __half* __restrict__ Y0, __half* __restrict__ Y1,
          __half* __restrict__ Y2, __half* __restrict__ Y3)
{
    int bid = blockIdx.x, tid = threadIdx.x;
    if (bid == 0 && tid < 64)
        g_invf[tid] = (float)pow(10000.0, -(double)tid / 64.0);

    if (bid < 8192) {
        conv_hi(x, Yx, bid * 256 + tid);
    } else {
        int w   = (bid - 8192) >> 12;            // 0..3
        int sub = (bid - 8192) & 4095;
        const float* W = (w == 0) ? W0 : (w == 1) ? W1 : (w == 2) ? W2 : W3;
        __half*      Y = (w == 0) ? Y0 : (w == 1) ? Y1 : (w == 2) ? Y2 : Y3;
        conv_hi(W, Y, sub * 256 + tid);
    }
}

// ===========================================================================
// GEMM mainloop: CTA 128x128, BK=64 (pitch 144B), 3-stage cp.async,
// 8 warps (2x4), warp 64x32. K'=2048 (32 slabs), stride 2048.
// ===========================================================================
#define SPITCH 144u
#define STG_OP (128u * SPITCH)          // 18432 B per operand per stage
#define STG_BOTH (2u * STG_OP)          // 36864 per stage
#define GSMEM (3u * STG_BOTH)           // 110592 total
#define KTN 32

__device__ __forceinline__
void gemm_mainloop(const __half* __restrict__ A,
                   const __half* __restrict__ B,
                   float c[4][4][4])
{
    extern __shared__ __align__(128) char gsm[];
    const uint32_t sbase = smem_to_u32(gsm);
    const int tid = threadIdx.x;
    const int lane = tid & 31, wid = tid >> 5;
    const int bm = blockIdx.y * 128, bn = blockIdx.x * 128;
    const int wm = (wid >> 2) * 64, wn = (wid & 3) * 32;

    const __half* Ag = A + ((size_t)bm << 11);
    const __half* Bg = B + ((size_t)bn << 11);

#pragma unroll
    for (int i = 0; i < 4; i++)
#pragma unroll
        for (int j = 0; j < 4; j++)
#pragma unroll
            for (int k = 0; k < 4; k++) c[i][j][k] = 0.f;

    const int frow = tid >> 3;          // 0..31 (+32*j)
    const int fseg = tid & 7;           // 0..7

#define GFILL(s) do {                                                         \
        uint32_t _st = sbase + (uint32_t)((s) % 3) * STG_BOTH;                \
        int _ks = (s) * 64;                                                   \
        _Pragma("unroll")                                                     \
        for (int _j = 0; _j < 4; _j++) {                                      \
            int _row = frow + _j * 32;                                        \
            uint32_t _d = (uint32_t)(_row * SPITCH + fseg * 16);              \
            const void* _ga = Ag + ((size_t)_row << 11) + _ks + fseg * 8;     \
            const void* _gb = Bg + ((size_t)_row << 11) + _ks + fseg * 8;     \
            cpa16(_st + _d, _ga); cpa16(_st + STG_OP + _d, _gb);              \
        }                                                                     \
        asm volatile("cp.async.commit_group;" ::: "memory");                  \
    } while (0)

    GFILL(0); GFILL(1);

    const uint32_t aRowOff = (uint32_t)((wm + (lane & 15)) * SPITCH);
    const uint32_t bRowOff = (uint32_t)((wn + (lane & 7) + ((lane >> 4) << 3)) * SPITCH);
    const uint32_t aColOff = (uint32_t)((lane >> 4) << 4);
    const uint32_t bColOff = (uint32_t)(((lane >> 3) & 1) << 4);

    for (int kt = 0; kt < KTN; kt++) {
        asm volatile("cp.async.wait_group 1;" ::: "memory");
        __syncthreads();
        if (kt + 2 < KTN) { GFILL(kt + 2); }
        else { asm volatile("cp.async.commit_group;" ::: "memory"); }

        const uint32_t st = sbase + (uint32_t)(kt % 3) * STG_BOTH;
        const uint32_t sa = st, sb = st + STG_OP;

#pragma unroll
        for (int ks = 0; ks < 4; ks++) {
            uint32_t a[4][4], bf[2][4];
            const uint32_t ac = ks * 32 + aColOff;
            const uint32_t bc = ks * 32 + bColOff;
#pragma unroll
            for (int mt = 0; mt < 4; mt++)
                LDSM4(a[mt], sa + aRowOff + (uint32_t)(mt * 16) * SPITCH + ac);
#pragma unroll
            for (int nt2 = 0; nt2 < 2; nt2++)
                LDSM4(bf[nt2], sb + bRowOff + (uint32_t)(nt2 * 16) * SPITCH + bc);
#pragma unroll
            for (int mt = 0; mt < 4; mt++)
#pragma unroll
                for (int nt = 0; nt < 4; nt++)
                    MMA16816(c[mt][nt], a[mt],
                             bf[nt >> 1][(nt & 1) * 2], bf[nt >> 1][(nt & 1) * 2 + 1]);
        }
    }
#undef GFILL
}

// ===========================================================================
// QKV GEMM with fused RoPE + scale epilogue; hi-only fp16 outputs.
// z=0: Q (rope+scale), z=1: K (rope), z=2: V.
// ===========================================================================
__global__ __launch_bounds__(256, 2)
void gemm_qkv_fused(const __half* __restrict__ A,
                    const __half* __restrict__ WQ, const __half* __restrict__ WK,
                    const __half* __restrict__ WV,
                    const int* __restrict__ pos)
{
    const int z = blockIdx.z;
    const __half* Bw = (z == 0) ? WQ : (z == 1) ? WK : WV;

    float c[4][4][4];
    gemm_mainloop(A, Bw, c);

    __half* HI = (z == 0) ? g_Qh : (z == 1) ? g_Kh : g_Vh;

    const int lane = threadIdx.x & 31, wid = threadIdx.x >> 5;
    const int bm = blockIdx.y * 128, bn = blockIdx.x * 128;
    const int wm = (wid >> 2) * 64, wn = (wid & 3) * 32;
    const int r0 = bm + wm + (lane >> 2);
    const int c0 = bn + wn + (lane & 3) * 2;

#pragma unroll
    for (int mt = 0; mt < 4; mt++) {
#pragma unroll
        for (int half = 0; half < 2; half++) {
            const int rr = r0 + mt * 16 + half * 8;
            const int b = rr >> 11, s = rr & 2047;
            const int p = pos[s];
#pragma unroll
            for (int nt = 0; nt < 4; nt++) {
                const int cc = c0 + nt * 8;
                const int h = cc >> 7, dk = cc & 127;
                float v0 = c[mt][nt][half * 2], v1 = c[mt][nt][half * 2 + 1];
                if (z < 2) {
                    const int i = dk >> 1;
                    float ang = (float)p * g_invf[i];
                    float sn, cs;
                    sincosf(ang, &sn, &cs);
                    float r1 = v0 * cs - v1 * sn;
                    float r2 = v0 * sn + v1 * cs;
                    v0 = r1; v1 = r2;
                    if (z == 0) { v0 *= SCALE; v1 *= SCALE; }
                }
                size_t dst = (((size_t)(b * 16 + h) << 11) + s) * 128 + dk;
                *(uint32_t*)(HI + dst) = pack_f16x2(v0, v1);
            }
        }
    }
}

// ===========================================================================
// Final GEMM: out = AOhi * Wohi^T, plain fp32 epilogue
// ===========================================================================
__global__ __launch_bounds__(256, 2)
void gemm_out(const __half* __restrict__ A, const __half* __restrict__ B,
              float* __restrict__ C)
{
    float c[4][4][4];
    gemm_mainloop(A, B, c);

    const int lane = threadIdx.x & 31, wid = threadIdx.x >> 5;
    const int bm = blockIdx.y * 128, bn = blockIdx.x * 128;
    const int wm = (wid >> 2) * 64, wn = (wid & 3) * 32;
    const int r0 = bm + wm + (lane >> 2);
    const int c0 = bn + wn + (lane & 3) * 2;
#pragma unroll
    for (int mt = 0; mt < 4; mt++)
#pragma unroll
        for (int nt = 0; nt < 4; nt++) {
            int rr = r0 + mt * 16, cc = c0 + nt * 8;
            *(float2*)(C + (size_t)rr * Dm + cc)       = make_float2(c[mt][nt][0], c[mt][nt][1]);
            *(float2*)(C + (size_t)(rr + 8) * Dm + cc) = make_float2(c[mt][nt][2], c[mt][nt][3]);
        }
}

// ===========================================================================
// Tensor-core flash attention, causal. Hi-only fp16: 1 QK + 1 PV pass.
// BQ=BKV=64, 128 threads, 3 tiles -> 4 CTA/SM.
// K(j+1) prefetch issued BEFORE PV(j): after the V-wait barrier all warps
// have provably finished their QK reads of the K tile, so overwriting it is
// safe and the K load overlaps the full PV block.
// ===========================================================================
#define FPB 272
#define TILEB ((uint32_t)(64 * FPB))   // 17408 bytes
#define FSMEM (3u * TILEB)             // 52224

__global__ __launch_bounds__(128, 4)
void flash_f16(const __half* __restrict__ Qh, const __half* __restrict__ Kh,
               const __half* __restrict__ Vh, __half* __restrict__ AO)
{
    extern __shared__ __align__(128) __half fsm[];
    const uint32_t sb = smem_to_u32(fsm);
    const uint32_t uQh = sb, uKh = sb + TILEB, uVh = sb + 2 * TILEB;

    const int tid = threadIdx.x, lane = tid & 31, wid = tid >> 5;
    const int qt = (int)gridDim.x - 1 - (int)blockIdx.x;
    const int bh = blockIdx.y;
    const int q0 = qt * 64;
    const size_t hbase = (size_t)bh * (2048 * 128);

#pragma unroll
    for (int i = 0; i < 8; i++) {
        int cc = tid + i * 128, row = cc >> 4, seg = cc & 15;
        uint32_t d = (uint32_t)(row * FPB + seg * 16);
        cpa16(uQh + d, Qh + hbase + (size_t)(q0 + row) * 128 + seg * 8);
    }
    asm volatile("cp.async.commit_group;" ::: "memory");

#define KFILL(jj) do {                                                         \
        int _c0 = (jj) * 64;                                                   \
        _Pragma("unroll")                                                      \
        for (int _i = 0; _i < 8; _i++) {                                       \
            int _cc = tid + _i * 128, _row = _cc >> 4, _seg = _cc & 15;        \
            uint32_t _d = (uint32_t)(_row * FPB + _seg * 16);                  \
            cpa16(uKh + _d, Kh + hbase + (size_t)(_c0 + _row) * 128 + _seg * 8); \
        }                                                                      \
        asm volatile("cp.async.commit_group;" ::: "memory");                   \
    } while (0)
#define VFILL(jj) do {                                                         \
        int _c0 = (jj) * 64;                                                   \
        _Pragma("unroll")                                                      \
        for (int _i = 0; _i < 8; _i++) {                                       \
            int _cc = tid + _i * 128, _row = _cc >> 4, _seg = _cc & 15;        \
            uint32_t _d = (uint32_t)(_row * FPB + _seg * 16);                  \
            cpa16(uVh + _d, Vh + hbase + (size_t)(_c0 + _row) * 128 + _seg * 8); \
        }                                                                      \
        asm volatile("cp.async.commit_group;" ::: "memory");                   \
    } while (0)

    KFILL(0); VFILL(0);

    float co[16][4];
#pragma unroll
    for (int i = 0; i < 16; i++)
#pragma unroll
        for (int k = 0; k < 4; k++) co[i][k] = 0.f;
    float m0v = -1e30f, m1v = -1e30f, l0v = 0.f, l1v = 0.f;

    const uint32_t aoff  = (uint32_t)((wid * 16 + (lane & 15)) * FPB + ((lane >> 4) << 4));
    const uint32_t bKoff = (uint32_t)(((lane & 7) + ((lane >> 4) << 3)) * FPB + (((lane >> 3) & 1) << 4));
    const uint32_t vloff = (uint32_t)((lane & 15) * FPB + ((lane >> 4) << 4));

    for (int j = 0; j <= qt; j++) {
        // K tile j ready (V j and possibly nothing else pending)
        asm volatile("cp.async.wait_group 1;" ::: "memory");
        __syncthreads();

        float cs[8][4];
#pragma unroll
        for (int i = 0; i < 8; i++)
#pragma unroll
            for (int k = 0; k < 4; k++) cs[i][k] = 0.f;

#pragma unroll
        for (int ks = 0; ks < 8; ks++) {
            uint32_t aH[4];
            LDSM4(aH, uQh + aoff + ks * 32);
#pragma unroll
            for (int np = 0; np < 4; np++) {
                uint32_t bH[4];
                uint32_t bo = bKoff + (uint32_t)(np * 16 * FPB) + ks * 32;
                LDSM4(bH, uKh + bo);
                MMA16816(cs[2*np],   aH, bH[0], bH[1]);
                MMA16816(cs[2*np+1], aH, bH[2], bH[3]);
            }
        }

        if (j == qt) {
            int g = lane >> 2, t2 = (lane & 3) * 2;
            int r0 = wid * 16 + g, r1 = r0 + 8;
#pragma unroll
            for (int nt = 0; nt < 8; nt++) {
                int cl = nt * 8 + t2;
                if (cl     > r0) cs[nt][0] = -1e30f;
                if (cl + 1 > r0) cs[nt][1] = -1e30f;
                if (cl     > r1) cs[nt][2] = -1e30f;
                if (cl + 1 > r1) cs[nt][3] = -1e30f;
            }
        }

        float mx0 = -1e30f, mx1 = -1e30f;
#pragma unroll
        for (int nt = 0; nt < 8; nt++) {
            mx0 = fmaxf(mx0, fmaxf(cs[nt][0], cs[nt][1]));
            mx1 = fmaxf(mx1, fmaxf(cs[nt][2], cs[nt][3]));
        }
        mx0 = fmaxf(mx0, __shfl_xor_sync(0xffffffffu, mx0, 1));
        mx0 = fmaxf(mx0, __shfl_xor_sync(0xffffffffu, mx0, 2));
        mx1 = fmaxf(mx1, __shfl_xor_sync(0xffffffffu, mx1, 1));
        mx1 = fmaxf(mx1, __shfl_xor_sync(0xffffffffu, mx1, 2));
        float mn0 = fmaxf(m0v, mx0), mn1 = fmaxf(m1v, mx1);
        float al0 = __expf(m0v - mn0), al1 = __expf(m1v - mn1);
        m0v = mn0; m1v = mn1;
        float rs0 = 0.f, rs1 = 0.f;
#pragma unroll
        for (int nt = 0; nt < 8; nt++) {
            cs[nt][0] = __expf(cs[nt][0] - mn0);
            cs[nt][1] = __expf(cs[nt][1] - mn0);
            cs[nt][2] = __expf(cs[nt][2] - mn1);
            cs[nt][3] = __expf(cs[nt][3] - mn1);
            rs0 += cs[nt][0] + cs[nt][1];
            rs1 += cs[nt][2] + cs[nt][3];
        }
        rs0 += __shfl_xor_sync(0xffffffffu, rs0, 1);
        rs0 += __shfl_xor_sync(0xffffffffu, rs0, 2);
        rs1 += __shfl_xor_sync(0xffffffffu, rs1, 1);
        rs1 += __shfl_xor_sync(0xffffffffu, rs1, 2);
        l0v = l0v * al0 + rs0;
        l1v = l1v * al1 + rs1;
#pragma unroll
        for (int nt = 0; nt < 16; nt++) {
            co[nt][0] *= al0; co[nt][1] *= al0;
            co[nt][2] *= al1; co[nt][3] *= al1;
        }

        // V tile j ready; after this barrier all warps are past QK -> safe
        // to start overwriting the K tile with j+1 (overlaps PV below).
        asm volatile("cp.async.wait_group 0;" ::: "memory");
        __syncthreads();
        if (j < qt) KFILL(j + 1);

#pragma unroll
        for (int ks = 0; ks < 4; ks++) {
            uint32_t aPh[4] = { pack_f16x2(cs[2*ks][0],   cs[2*ks][1]),
                                pack_f16x2(cs[2*ks][2],   cs[2*ks][3]),
                                pack_f16x2(cs[2*ks+1][0], cs[2*ks+1][1]),
                                pack_f16x2(cs[2*ks+1][2], cs[2*ks+1][3]) };
            uint32_t vb = vloff + (uint32_t)(ks * 16 * FPB);
#pragma unroll
            for (int dc = 0; dc < 8; dc++) {
                uint32_t vH[4];
                LDSM4T(vH, uVh + vb + dc * 32);
                MMA16816(co[2*dc],   aPh, vH[0], vH[1]);
                MMA16816(co[2*dc+1], aPh, vH[2], vH[3]);
            }
        }

        __syncthreads();
        if (j < qt) VFILL(j + 1);
    }
#undef KFILL
#undef VFILL

    // ---- epilogue: write AO hi-only fp16 (stride 2048) ----
    float i0 = 1.f / l0v, i1 = 1.f / l1v;
    const int b = bh >> 4, h = bh & 15;
    int g = lane >> 2, t2 = (lane & 3) * 2;
    const int r0 = b * 2048 + q0 + wid * 16 + g;
    const int cbase = h * 128 + t2;
#pragma unroll
    for (int nt = 0; nt < 16; nt++) {
        const int cc = cbase + nt * 8;
        *(uint32_t*)(AO + ((size_t)r0 << 11) + cc) =
            pack_f16x2(co[nt][0] * i0, co[nt][1] * i0);
        *(uint32_t*)(AO + ((size_t)(r0 + 8) << 11) + cc) =
            pack_f16x2(co[nt][2] * i1, co[nt][3] * i1);
    }
}

// ===========================================================================
extern "C" void kernel_launch(void* const* d_in, const int* in_sizes, int n_in,
                              void* d_out, int out_size)
{
    const float* x  = (const float*)d_in[0];
    const float* WQ = (const float*)d_in[1];
    const float* WK = (const float*)d_in[2];
    const float* WV = (const float*)d_in[3];
    const float* WO = (const float*)d_in[4];
    const int*  pos = (const int*)d_in[5];
    float* out = (float*)d_out;

    __half *Axp, *Aaop, *Wqp, *Wkp, *Wvp, *Wop;
    __half *Qhp, *Khp, *Vhp;
    cudaGetSymbolAddress((void**)&Axp, g_Ax);
    cudaGetSymbolAddress((void**)&Aaop, g_Aao);
    cudaGetSymbolAddress((void**)&Wqp, g_Wq);
    cudaGetSymbolAddress((void**)&Wkp, g_Wk);
    cudaGetSymbolAddress((void**)&Wvp, g_Wv);
    cudaGetSymbolAddress((void**)&Wop, g_Wo);
    cudaGetSymbolAddress((void**)&Qhp, g_Qh);
    cudaGetSymbolAddress((void**)&Khp, g_Kh);
    cudaGetSymbolAddress((void**)&Vhp, g_Vh);

    prep<<<8192 + 4 * 4096, 256>>>(x, WQ, WK, WV, WO, Axp, Wqp, Wkp, Wvp, Wop);

    cudaFuncSetAttribute(gemm_qkv_fused, cudaFuncAttributeMaxDynamicSharedMemorySize, GSMEM);
    cudaFuncSetAttribute(gemm_out,       cudaFuncAttributeMaxDynamicSharedMemorySize, GSMEM);

    gemm_qkv_fused<<<dim3(Dm / 128, Mrows / 128, 3), 256, GSMEM>>>(Axp, Wqp, Wkp, Wvp, pos);

    cudaFuncSetAttribute(flash_f16, cudaFuncAttributeMaxDynamicSharedMemorySize, FSMEM);
    flash_f16<<<dim3(Sseq / 64, Bb * Hh), 128, FSMEM>>>(Qhp, Khp, Vhp, Aaop);

    gemm_out<<<dim3(Dm / 128, Mrows / 128), 256, GSMEM>>>(Aaop, Wop, out);
}